// round 1
// baseline (speedup 1.0000x reference)
#include <cuda_runtime.h>
#include <math.h>

// ---------------- problem constants ----------------
constexpr int BATCH = 4;
constexpr int SEQ   = 4096;
constexpr int DIM   = 256;
constexpr int DFF   = 1024;
constexpr int NTOK  = BATCH * SEQ;                 // 16384
constexpr size_t TXT_N = (size_t)NTOK * DIM;       // 4,194,304
constexpr int IMG_N = BATCH * 196 * DIM;           // 200,704

// ---------------- scratch (device globals; no allocs allowed) ----------------
__device__ float g_Q [4194304];
__device__ float g_K [4194304];
__device__ float g_V [4194304];
__device__ float g_SK[4194304];
__device__ float g_O [4194304];
__device__ float g_H [4194304];
__device__ float g_M2[4194304];
__device__ float g_FF[16777216];                   // [16384, 1024]
__device__ float g_att[67108864];                  // [4, 4096, 4096]
__device__ float g_part[4096];                     // 2048 sums + 2048 sumsq
__device__ float g_stats[2];
__device__ float g_P [BATCH * 4 * DIM];            // prefix sums at {2047,2048,2049,2052}
__device__ float g_pp[BATCH * 16 * DIM];           // chunked partials

// ---------------- generic fp32 GEMM: C = alpha * A @ op(B) (+bias)(+relu) ----------------
// A: [M,K] row-major.  TRANSB: B is [N,K] (C=A·B^T).  !TRANSB: B is [K,N] (C=A·B).
// BM=BN=128, BK=16, 256 threads, 8x8 per thread. Dims assumed multiples of tiles.
template<bool TRANSB>
__global__ void __launch_bounds__(256) sgemm(
    const float* __restrict__ A, const float* __restrict__ B,
    float* __restrict__ C, int M, int N, int K,
    size_t sA, size_t sB, size_t sC,
    float alpha, const float* __restrict__ bias, int relu)
{
    __shared__ float As[16][128];
    __shared__ float Bs[16][128];
    const int tid = threadIdx.x;
    const int bx = blockIdx.x, by = blockIdx.y, bz = blockIdx.z;
    const float* Ab = A + (size_t)bz * sA + (size_t)by * 128 * K;
    const float* Bb = B + (size_t)bz * sB;
    float*       Cb = C + (size_t)bz * sC;
    const int tm = (tid >> 4) << 3;
    const int tn = (tid & 15) << 3;

    float acc[8][8];
#pragma unroll
    for (int i = 0; i < 8; i++)
#pragma unroll
        for (int j = 0; j < 8; j++) acc[i][j] = 0.f;

    for (int k0 = 0; k0 < K; k0 += 16) {
#pragma unroll
        for (int l = 0; l < 2; l++) {                       // A tile: 128x16
            int idx = (tid + l * 256) << 2;
            int m  = idx >> 4;
            int kk = idx & 15;
            float4 v = *(const float4*)(Ab + (size_t)m * K + k0 + kk);
            As[kk + 0][m] = v.x; As[kk + 1][m] = v.y;
            As[kk + 2][m] = v.z; As[kk + 3][m] = v.w;
        }
        if (TRANSB) {
#pragma unroll
            for (int l = 0; l < 2; l++) {                   // B tile from [N,K]
                int idx = (tid + l * 256) << 2;
                int n  = idx >> 4;
                int kk = idx & 15;
                float4 v = *(const float4*)(Bb + (size_t)(bx * 128 + n) * K + k0 + kk);
                Bs[kk + 0][n] = v.x; Bs[kk + 1][n] = v.y;
                Bs[kk + 2][n] = v.z; Bs[kk + 3][n] = v.w;
            }
        } else {
#pragma unroll
            for (int l = 0; l < 2; l++) {                   // B tile from [K,N]
                int idx = (tid + l * 256) << 2;
                int kk = idx >> 7;
                int n  = idx & 127;
                *(float4*)&Bs[kk][n] =
                    *(const float4*)(Bb + (size_t)(k0 + kk) * N + bx * 128 + n);
            }
        }
        __syncthreads();
#pragma unroll
        for (int kk = 0; kk < 16; kk++) {
            float a[8], b[8];
#pragma unroll
            for (int i = 0; i < 8; i++) a[i] = As[kk][tm + i];
#pragma unroll
            for (int j = 0; j < 8; j++) b[j] = Bs[kk][tn + j];
#pragma unroll
            for (int i = 0; i < 8; i++)
#pragma unroll
                for (int j = 0; j < 8; j++) acc[i][j] = fmaf(a[i], b[j], acc[i][j]);
        }
        __syncthreads();
    }

#pragma unroll
    for (int i = 0; i < 8; i++) {
        size_t row = (size_t)(by * 128 + tm + i);
#pragma unroll
        for (int j = 0; j < 8; j += 4) {
            float4 v;
            float* pv = &v.x;
#pragma unroll
            for (int jj = 0; jj < 4; jj++) {
                float x = acc[i][j + jj] * alpha;
                if (bias) x += bias[bx * 128 + tn + j + jj];
                if (relu) x = fmaxf(x, 0.f);
                pv[jj] = x;
            }
            *(float4*)(Cb + row * N + bx * 128 + tn + j) = v;
        }
    }
}

// ---------------- prefix sums of K rows (for analytic sparse@K) ----------------
__global__ void prefix_partial(const float* __restrict__ Kmat, float* __restrict__ pp) {
    int ch = blockIdx.x, b = blockIdx.y, d = threadIdx.x;   // 16 chunks cover rows [0,2047)
    int s0 = ch * 128;
    int s1 = min(s0 + 128, 2047);
    const float* Kb = Kmat + (size_t)b * SEQ * DIM;
    float s = 0.f;
    for (int ss = s0; ss < s1; ss++) s += Kb[(size_t)ss * DIM + d];
    pp[((size_t)b * 16 + ch) * DIM + d] = s;
}

__global__ void prefix_combine(const float* __restrict__ Kmat,
                               const float* __restrict__ pp, float* __restrict__ P) {
    int b = blockIdx.x, d = threadIdx.x;
    const float* Kb = Kmat + (size_t)b * SEQ * DIM;
    float s = 0.f;
    for (int ch = 0; ch < 16; ch++) s += pp[((size_t)b * 16 + ch) * DIM + d];
    float p2047 = s;
    float p2048 = p2047 + Kb[(size_t)2047 * DIM + d];
    float p2049 = p2048 + Kb[(size_t)2048 * DIM + d];
    float p2052 = p2049 + Kb[(size_t)2049 * DIM + d]
                        + Kb[(size_t)2050 * DIM + d]
                        + Kb[(size_t)2051 * DIM + d];
    float* Pb = P + (size_t)b * 4 * DIM;
    Pb[0 * DIM + d] = p2047;
    Pb[1 * DIM + d] = p2048;
    Pb[2 * DIM + d] = p2049;
    Pb[3 * DIM + d] = p2052;
}

// sk[b,i,:] = a(n)*bandsum + b(n)*offsum
__global__ void sk_kernel(const float* __restrict__ Kmat, const float* __restrict__ P,
                          float* __restrict__ SK,
                          float A3, float B3, float A4, float B4, float A5, float B5) {
    int i = blockIdx.x, b = blockIdx.y, d = threadIdx.x;
    const float* Kb = Kmat + (size_t)b * SEQ * DIM;
    int lo = max(i - 2, 0), hi = min(i + 2, SEQ - 1);
    int n = hi - lo + 1;
    float band = 0.f;
    for (int j = lo; j <= hi; j++) band += Kb[(size_t)j * DIM + d];
    const float* Pb = P + (size_t)b * 4 * DIM;
    float off;
    if (i <= 2048) off = Pb[3 * DIM + d] - band;            // [0,2052) \ band
    else           off = Pb[(5 - n) * DIM + d];             // [0, 2052-n)
    float a, bb;
    if (n == 5)      { a = A5; bb = B5; }
    else if (n == 4) { a = A4; bb = B4; }
    else             { a = A3; bb = B3; }
    SK[((size_t)b * SEQ + i) * DIM + d] = a * band + bb * off;
}

// ---------------- row softmax over 4096 cols, row cached in smem ----------------
__global__ void __launch_bounds__(256) softmax_rows(float* __restrict__ att) {
    __shared__ float row[4096];
    __shared__ float red[8];
    size_t r = blockIdx.x;
    float* p = att + r * 4096;
    int tid = threadIdx.x;

    float mx = -1e30f;
    for (int c = tid; c < 4096; c += 256) { float v = p[c]; row[c] = v; mx = fmaxf(mx, v); }
#pragma unroll
    for (int o = 16; o; o >>= 1) mx = fmaxf(mx, __shfl_xor_sync(0xffffffffu, mx, o));
    if ((tid & 31) == 0) red[tid >> 5] = mx;
    __syncthreads();
    float bmx = red[0];
#pragma unroll
    for (int w = 1; w < 8; w++) bmx = fmaxf(bmx, red[w]);
    __syncthreads();

    float s = 0.f;
    for (int c = tid; c < 4096; c += 256) { float e = __expf(row[c] - bmx); row[c] = e; s += e; }
#pragma unroll
    for (int o = 16; o; o >>= 1) s += __shfl_xor_sync(0xffffffffu, s, o);
    if ((tid & 31) == 0) red[tid >> 5] = s;
    __syncthreads();
    float bs = 0.f;
#pragma unroll
    for (int w = 0; w < 8; w++) bs += red[w];
    float inv = 1.f / bs;
    for (int c = tid; c < 4096; c += 256) p[c] = row[c] * inv;
}

// ---------------- full-tensor LayerNorm (over all B*S*D elements) ----------------
__global__ void ln_partial(const float* __restrict__ x1, const float* __restrict__ x2,
                           float* __restrict__ part) {
    int tid = threadIdx.x, bid = blockIdx.x;
    float s = 0.f, ss = 0.f;
    for (size_t i = (size_t)bid * 256 + tid; i < TXT_N; i += (size_t)2048 * 256) {
        float v = x1[i] + x2[i];
        s += v;
        ss = fmaf(v, v, ss);
    }
    __shared__ float rs[256], rss[256];
    rs[tid] = s; rss[tid] = ss;
    __syncthreads();
    for (int o = 128; o; o >>= 1) {
        if (tid < o) { rs[tid] += rs[tid + o]; rss[tid] += rss[tid + o]; }
        __syncthreads();
    }
    if (tid == 0) { part[bid] = rs[0]; part[2048 + bid] = rss[0]; }
}

__global__ void ln_combine(const float* __restrict__ part, float* __restrict__ stats) {
    __shared__ double sd[256], ssd[256];
    int tid = threadIdx.x;
    double s = 0.0, ss = 0.0;
    for (int i = tid; i < 2048; i += 256) { s += part[i]; ss += part[2048 + i]; }
    sd[tid] = s; ssd[tid] = ss;
    __syncthreads();
    for (int o = 128; o; o >>= 1) {
        if (tid < o) { sd[tid] += sd[tid + o]; ssd[tid] += ssd[tid + o]; }
        __syncthreads();
    }
    if (tid == 0) {
        double n = (double)TXT_N;
        double mu = sd[0] / n;
        double var = ssd[0] / n - mu * mu;
        stats[0] = (float)mu;
        stats[1] = (float)(1.0 / sqrt(var + 1e-6));
    }
}

__global__ void ln_apply(const float* __restrict__ x1, const float* __restrict__ x2,
                         const float* __restrict__ g, const float* __restrict__ bta,
                         const float* __restrict__ stats, float* __restrict__ out) {
    size_t i = (size_t)blockIdx.x * 256 + threadIdx.x;
    float mu = stats[0], r = stats[1];
    float v = x1[i] + x2[i];
    out[i] = (v - mu) * r * g[i] + bta[i];
}

__global__ void copy_img(const float* __restrict__ src, float* __restrict__ dst, int n) {
    int i = blockIdx.x * 256 + threadIdx.x;
    if (i < n) dst[i] = src[i];
}

// ---------------- launch ----------------
extern "C" void kernel_launch(void* const* d_in, const int* in_sizes, int n_in,
                              void* d_out, int out_size) {
    const float* text  = (const float*)d_in[0];
    const float* image = (const float*)d_in[1];
    const float* Wq = (const float*)d_in[2];
    const float* bq = (const float*)d_in[3];
    const float* Wk = (const float*)d_in[4];
    const float* bk = (const float*)d_in[5];
    const float* Wv = (const float*)d_in[6];
    const float* bv = (const float*)d_in[7];
    const float* W1 = (const float*)d_in[8];
    const float* b1 = (const float*)d_in[9];
    const float* W2 = (const float*)d_in[10];
    const float* b2 = (const float*)d_in[11];
    const float* gamma = (const float*)d_in[12];
    const float* beta  = (const float*)d_in[13];
    float* out = (float*)d_out;

    float *Q, *K, *V, *SK, *O, *H, *M2, *FF, *att, *part, *stats, *P, *pp;
    cudaGetSymbolAddress((void**)&Q,  g_Q);
    cudaGetSymbolAddress((void**)&K,  g_K);
    cudaGetSymbolAddress((void**)&V,  g_V);
    cudaGetSymbolAddress((void**)&SK, g_SK);
    cudaGetSymbolAddress((void**)&O,  g_O);
    cudaGetSymbolAddress((void**)&H,  g_H);
    cudaGetSymbolAddress((void**)&M2, g_M2);
    cudaGetSymbolAddress((void**)&FF, g_FF);
    cudaGetSymbolAddress((void**)&att, g_att);
    cudaGetSymbolAddress((void**)&part, g_part);
    cudaGetSymbolAddress((void**)&stats, g_stats);
    cudaGetSymbolAddress((void**)&P,  g_P);
    cudaGetSymbolAddress((void**)&pp, g_pp);

    // sparse-softmax coefficients (depend only on band count n)
    double e = exp(1.0);
    float A[6], Bc[6];
    for (int n = 3; n <= 5; n++) {
        double Z = n * e + (double)(SEQ - n);
        A[n]  = (float)(e / Z);
        Bc[n] = (float)(1.0 / Z);
    }

    // QKV projections: [16384,256] @ [256,256]^T + bias
    sgemm<true><<<dim3(2, 128, 1), 256>>>(text, Wq, Q, NTOK, DIM, DIM, 0, 0, 0, 1.f, bq, 0);
    sgemm<true><<<dim3(2, 128, 1), 256>>>(text, Wk, K, NTOK, DIM, DIM, 0, 0, 0, 1.f, bk, 0);
    sgemm<true><<<dim3(2, 128, 1), 256>>>(text, Wv, V, NTOK, DIM, DIM, 0, 0, 0, 1.f, bv, 0);

    // analytic sparse @ K
    prefix_partial<<<dim3(16, BATCH), 256>>>(K, pp);
    prefix_combine<<<BATCH, 256>>>(K, pp, P);
    sk_kernel<<<dim3(SEQ, BATCH), 256>>>(K, P, SK, A[3], Bc[3], A[4], Bc[4], A[5], Bc[5]);

    // att = Q @ SK^T / 16  (batched)
    sgemm<true><<<dim3(32, 32, BATCH), 256>>>(Q, SK, att, SEQ, SEQ, DIM,
                                              (size_t)SEQ * DIM, (size_t)SEQ * DIM,
                                              (size_t)SEQ * SEQ, 0.0625f, nullptr, 0);
    softmax_rows<<<NTOK, 256>>>(att);

    // O = att @ V (batched, NN)
    sgemm<false><<<dim3(2, 32, BATCH), 256>>>(att, V, O, SEQ, DIM, SEQ,
                                              (size_t)SEQ * SEQ, (size_t)SEQ * DIM,
                                              (size_t)SEQ * DIM, 1.f, nullptr, 0);

    // LN1 over full tensor of (O + text) -> H
    ln_partial<<<2048, 256>>>(O, text, part);
    ln_combine<<<1, 256>>>(part, stats);
    ln_apply<<<NTOK, 256>>>(O, text, gamma, beta, stats, H);

    // MLP
    sgemm<true><<<dim3(8, 128, 1), 256>>>(H, W1, FF, NTOK, DFF, DIM, 0, 0, 0, 1.f, b1, 1);
    sgemm<true><<<dim3(2, 128, 1), 256>>>(FF, W2, M2, NTOK, DIM, DFF, 0, 0, 0, 1.f, b2, 0);

    // LN2 over full tensor of (M2 + text) -> d_out (text part)
    ln_partial<<<2048, 256>>>(M2, text, part);
    ln_combine<<<1, 256>>>(part, stats);
    ln_apply<<<NTOK, 256>>>(M2, text, gamma, beta, stats, out);

    // image passthrough
    if (out_size >= (int)TXT_N + IMG_N) {
        copy_img<<<(IMG_N + 255) / 256, 256>>>(image, out + TXT_N, IMG_N);
    }
}

// round 4
// speedup vs baseline: 2.6146x; 2.6146x over previous
#include <cuda_runtime.h>
#include <math.h>
#include <stdint.h>

// ---------------- problem constants ----------------
constexpr int BATCH = 4;
constexpr int SEQ   = 4096;
constexpr int DIM   = 256;
constexpr int DFF   = 1024;
constexpr int NTOK  = BATCH * SEQ;                 // 16384
constexpr size_t TXT_N = (size_t)NTOK * DIM;       // 4,194,304
constexpr int IMG_N = BATCH * 196 * DIM;           // 200,704

// ---------------- scratch (device globals; no allocs allowed) ----------------
__device__ float g_Q [4194304];
__device__ float g_K [4194304];
__device__ float g_V [4194304];
__device__ float g_Vt[4194304];
__device__ float g_SK[4194304];
__device__ float g_O [4194304];
__device__ float g_H [4194304];
__device__ float g_M2[4194304];
__device__ float g_FF[16777216];                   // [16384, 1024]
__device__ float g_att[67108864];                  // [4, 4096, 4096]
__device__ float g_part[4096];
__device__ float g_stats[2];
__device__ float g_P [BATCH * 4 * DIM];
__device__ float g_pp[BATCH * 16 * DIM];

// ================= async copy helpers (baseline PTX, sm_80+) =================
__device__ __forceinline__ uint32_t smem_u32(const void* p) {
    uint32_t a;
    asm("{ .reg .u64 t; cvta.to.shared.u64 t, %1; cvt.u32.u64 %0, t; }" : "=r"(a) : "l"(p));
    return a;
}
#define CP16(dst, src) \
    asm volatile("cp.async.cg.shared.global [%0], [%1], 16;" :: "r"(dst), "l"(src))
#define CP_COMMIT() asm volatile("cp.async.commit_group;" ::: "memory")
#define CP_WAIT(n)  asm volatile("cp.async.wait_group %0;" :: "n"(n) : "memory")

// mma.sync m16n8k8 tf32 (row.col): D += A*B
__device__ __forceinline__ void mma8(float* c, uint32_t a0, uint32_t a1,
                                     uint32_t a2, uint32_t a3, uint32_t b0, uint32_t b1) {
    asm volatile(
        "mma.sync.aligned.m16n8k8.row.col.f32.tf32.tf32.f32 "
        "{%0,%1,%2,%3}, {%4,%5,%6,%7}, {%8,%9}, {%0,%1,%2,%3};\n"
        : "+f"(c[0]), "+f"(c[1]), "+f"(c[2]), "+f"(c[3])
        : "r"(a0), "r"(a1), "r"(a2), "r"(a3), "r"(b0), "r"(b1));
}

// ================= tf32 tensor-core GEMM: C = alpha*A@B^T (+bias)(+relu) ======
// A: [M,K] row-major, B: [N,K] row-major. CTA tile 128x128, BK=32, 2-stage cp.async.
// 8 warps: 4 in M x 2 in N, warp tile 32x64.
constexpr int TCBM = 128, TCBN = 128, TCBK = 32;
constexpr int ASTRIDE = 36;                         // floats per smem row (pad 4)
constexpr int STAGE_BYTES = 128 * ASTRIDE * 4;      // 18432
constexpr int GEMM_SMEM = 4 * STAGE_BYTES;          // A0 A1 B0 B1 = 73728

__device__ __forceinline__ void load_stage_tc(
    uint32_t smA, uint32_t smB,
    const float* __restrict__ Ab, const float* __restrict__ Bb,
    int K, int k0, int tid)
{
#pragma unroll
    for (int it = 0; it < 4; it++) {
        int idx = tid + it * 256;                   // 0..1023
        int row = idx >> 3, seg = idx & 7;
        CP16(smA + (uint32_t)(row * ASTRIDE + seg * 4) * 4,
             Ab + (size_t)row * K + k0 + seg * 4);
    }
#pragma unroll
    for (int it = 0; it < 4; it++) {
        int idx = tid + it * 256;
        int row = idx >> 3, seg = idx & 7;
        CP16(smB + (uint32_t)(row * ASTRIDE + seg * 4) * 4,
             Bb + (size_t)row * K + k0 + seg * 4);
    }
}

__global__ void __launch_bounds__(256) tc_gemm(
    const float* __restrict__ A, const float* __restrict__ B, float* __restrict__ C,
    int M, int N, int K, long long sA, long long sB, long long sC,
    float alpha, const float* __restrict__ bias, int relu)
{
    extern __shared__ char smem[];
    const int tid = threadIdx.x;
    const int wid = tid >> 5, lane = tid & 31;
    const int wm = wid & 3, wn = wid >> 2;          // 4 x 2 warp grid
    const int g = lane >> 2;                        // groupID (0..7)
    const int tg = lane & 3;                        // threadID_in_group (0..3)
    const int t2 = tg << 1;
    const int bx = blockIdx.x, by = blockIdx.y, bz = blockIdx.z;
    const int m0 = by * TCBM, n0 = bx * TCBN;
    const float* Ab = A + (size_t)bz * sA + (size_t)m0 * K;
    const float* Bb = B + (size_t)bz * sB + (size_t)n0 * K;
    float*       Cb = C + (size_t)bz * sC;

    const uint32_t sbase = smem_u32(smem);
    const uint32_t smA[2] = { sbase, sbase + STAGE_BYTES };
    const uint32_t smB[2] = { sbase + 2 * STAGE_BYTES, sbase + 3 * STAGE_BYTES };

    float acc[2][8][4];
#pragma unroll
    for (int i = 0; i < 2; i++)
#pragma unroll
        for (int j = 0; j < 8; j++)
#pragma unroll
            for (int v = 0; v < 4; v++) acc[i][j][v] = 0.f;

    const int KT = K / TCBK;
    load_stage_tc(smA[0], smB[0], Ab, Bb, K, 0, tid);
    CP_COMMIT();

    for (int kt = 0; kt < KT; kt++) {
        const int cur = kt & 1;
        if (kt + 1 < KT) {
            load_stage_tc(smA[cur ^ 1], smB[cur ^ 1], Ab, Bb, K, (kt + 1) * TCBK, tid);
            CP_COMMIT();
            CP_WAIT(1);
        } else {
            CP_WAIT(0);
        }
        __syncthreads();

        const float* As = (const float*)(smem + (size_t)cur * STAGE_BYTES);
        const float* Bs = (const float*)(smem + (size_t)(2 + cur) * STAGE_BYTES);
#pragma unroll
        for (int step = 0; step < 4; step++) {
            const int k0 = step * 8;
            // tf32 m16n8k8 A fragment: a0=A[g][t], a1=A[g+8][t], a2=A[g][t+4], a3=A[g+8][t+4]
            uint32_t afr[2][4];
#pragma unroll
            for (int i = 0; i < 2; i++) {
                int r = wm * 32 + i * 16 + g;
                afr[i][0] = __float_as_uint(As[r * ASTRIDE + k0 + tg]);
                afr[i][1] = __float_as_uint(As[(r + 8) * ASTRIDE + k0 + tg]);
                afr[i][2] = __float_as_uint(As[r * ASTRIDE + k0 + tg + 4]);
                afr[i][3] = __float_as_uint(As[(r + 8) * ASTRIDE + k0 + tg + 4]);
            }
#pragma unroll
            for (int j = 0; j < 8; j++) {
                // B fragment (col): b0=B[k=t][n=g], b1=B[k=t+4][n=g]; smem holds B as [n][k]
                int n = wn * 64 + j * 8 + g;
                uint32_t b0 = __float_as_uint(Bs[n * ASTRIDE + k0 + tg]);
                uint32_t b1 = __float_as_uint(Bs[n * ASTRIDE + k0 + tg + 4]);
#pragma unroll
                for (int i = 0; i < 2; i++) {
                    mma8(acc[i][j], afr[i][0], afr[i][1], afr[i][2], afr[i][3], b0, b1);
                }
            }
        }
        __syncthreads();
    }

    // epilogue: c0:(g, t2), c1:(g, t2+1), c2:(g+8, t2), c3:(g+8, t2+1)
#pragma unroll
    for (int i = 0; i < 2; i++) {
        int r = m0 + wm * 32 + i * 16 + g;
        float* crow0 = Cb + (size_t)r * N;
        float* crow1 = crow0 + (size_t)8 * N;
#pragma unroll
        for (int j = 0; j < 8; j++) {
            int c = n0 + wn * 64 + j * 8 + t2;
            float2 v0, v1;
            v0.x = acc[i][j][0] * alpha; v0.y = acc[i][j][1] * alpha;
            v1.x = acc[i][j][2] * alpha; v1.y = acc[i][j][3] * alpha;
            if (bias) {
                float bb0 = __ldg(bias + c), bb1 = __ldg(bias + c + 1);
                v0.x += bb0; v0.y += bb1;
                v1.x += bb0; v1.y += bb1;
            }
            if (relu) {
                v0.x = fmaxf(v0.x, 0.f); v0.y = fmaxf(v0.y, 0.f);
                v1.x = fmaxf(v1.x, 0.f); v1.y = fmaxf(v1.y, 0.f);
            }
            *(float2*)(crow0 + c) = v0;
            *(float2*)(crow1 + c) = v1;
        }
    }
}

// ---------------- V transpose: Vt[b,d,s] = V[b,s,d] ----------------
__global__ void transpose_v(const float* __restrict__ V, float* __restrict__ Vt) {
    __shared__ float t[32][33];
    int b = blockIdx.z;
    int s0 = blockIdx.x * 32, d0 = blockIdx.y * 32;
    const float* Vb = V + (size_t)b * SEQ * DIM;
    float* Vtb = Vt + (size_t)b * SEQ * DIM;
    int x = threadIdx.x, y = threadIdx.y;
#pragma unroll
    for (int i = 0; i < 32; i += 8)
        t[y + i][x] = Vb[(size_t)(s0 + y + i) * DIM + d0 + x];
    __syncthreads();
#pragma unroll
    for (int i = 0; i < 32; i += 8)
        Vtb[(size_t)(d0 + y + i) * SEQ + s0 + x] = t[x][y + i];
}

// ---------------- prefix sums of K rows (analytic sparse@K) ----------------
__global__ void prefix_partial(const float* __restrict__ Kmat, float* __restrict__ pp) {
    int ch = blockIdx.x, b = blockIdx.y, d = threadIdx.x;
    int s0 = ch * 128;
    int s1 = min(s0 + 128, 2047);
    const float* Kb = Kmat + (size_t)b * SEQ * DIM;
    float s = 0.f;
    for (int ss = s0; ss < s1; ss++) s += Kb[(size_t)ss * DIM + d];
    pp[((size_t)b * 16 + ch) * DIM + d] = s;
}

__global__ void prefix_combine(const float* __restrict__ Kmat,
                               const float* __restrict__ pp, float* __restrict__ P) {
    int b = blockIdx.x, d = threadIdx.x;
    const float* Kb = Kmat + (size_t)b * SEQ * DIM;
    float s = 0.f;
    for (int ch = 0; ch < 16; ch++) s += pp[((size_t)b * 16 + ch) * DIM + d];
    float p2047 = s;
    float p2048 = p2047 + Kb[(size_t)2047 * DIM + d];
    float p2049 = p2048 + Kb[(size_t)2048 * DIM + d];
    float p2052 = p2049 + Kb[(size_t)2049 * DIM + d]
                        + Kb[(size_t)2050 * DIM + d]
                        + Kb[(size_t)2051 * DIM + d];
    float* Pb = P + (size_t)b * 4 * DIM;
    Pb[0 * DIM + d] = p2047;
    Pb[1 * DIM + d] = p2048;
    Pb[2 * DIM + d] = p2049;
    Pb[3 * DIM + d] = p2052;
}

__global__ void sk_kernel(const float* __restrict__ Kmat, const float* __restrict__ P,
                          float* __restrict__ SK,
                          float A3, float B3, float A4, float B4, float A5, float B5) {
    int i = blockIdx.x, b = blockIdx.y, d = threadIdx.x;
    const float* Kb = Kmat + (size_t)b * SEQ * DIM;
    int lo = max(i - 2, 0), hi = min(i + 2, SEQ - 1);
    int n = hi - lo + 1;
    float band = 0.f;
    for (int j = lo; j <= hi; j++) band += Kb[(size_t)j * DIM + d];
    const float* Pb = P + (size_t)b * 4 * DIM;
    float off;
    if (i <= 2048) off = Pb[3 * DIM + d] - band;
    else           off = Pb[(5 - n) * DIM + d];
    float a, bb;
    if (n == 5)      { a = A5; bb = B5; }
    else if (n == 4) { a = A4; bb = B4; }
    else             { a = A3; bb = B3; }
    SK[((size_t)b * SEQ + i) * DIM + d] = a * band + bb * off;
}

// ---------------- row softmax over 4096 cols ----------------
__global__ void __launch_bounds__(256) softmax_rows(float* __restrict__ att) {
    __shared__ float row[4096];
    __shared__ float red[8];
    size_t r = blockIdx.x;
    float* p = att + r * 4096;
    int tid = threadIdx.x;

    float mx = -1e30f;
    for (int c = tid; c < 4096; c += 256) { float v = p[c]; row[c] = v; mx = fmaxf(mx, v); }
#pragma unroll
    for (int o = 16; o; o >>= 1) mx = fmaxf(mx, __shfl_xor_sync(0xffffffffu, mx, o));
    if ((tid & 31) == 0) red[tid >> 5] = mx;
    __syncthreads();
    float bmx = red[0];
#pragma unroll
    for (int w = 1; w < 8; w++) bmx = fmaxf(bmx, red[w]);
    __syncthreads();

    float s = 0.f;
    for (int c = tid; c < 4096; c += 256) { float e = __expf(row[c] - bmx); row[c] = e; s += e; }
#pragma unroll
    for (int o = 16; o; o >>= 1) s += __shfl_xor_sync(0xffffffffu, s, o);
    if ((tid & 31) == 0) red[tid >> 5] = s;
    __syncthreads();
    float bs = 0.f;
#pragma unroll
    for (int w = 0; w < 8; w++) bs += red[w];
    float inv = 1.f / bs;
    for (int c = tid; c < 4096; c += 256) p[c] = row[c] * inv;
}

// ---------------- full-tensor LayerNorm ----------------
__global__ void ln_partial(const float* __restrict__ x1, const float* __restrict__ x2,
                           float* __restrict__ part) {
    int tid = threadIdx.x, bid = blockIdx.x;
    float s = 0.f, ss = 0.f;
    for (size_t i = (size_t)bid * 256 + tid; i < TXT_N; i += (size_t)2048 * 256) {
        float v = x1[i] + x2[i];
        s += v;
        ss = fmaf(v, v, ss);
    }
    __shared__ float rs[256], rss[256];
    rs[tid] = s; rss[tid] = ss;
    __syncthreads();
    for (int o = 128; o; o >>= 1) {
        if (tid < o) { rs[tid] += rs[tid + o]; rss[tid] += rss[tid + o]; }
        __syncthreads();
    }
    if (tid == 0) { part[bid] = rs[0]; part[2048 + bid] = rss[0]; }
}

__global__ void ln_combine(const float* __restrict__ part, float* __restrict__ stats) {
    __shared__ double sd[256], ssd[256];
    int tid = threadIdx.x;
    double s = 0.0, ss = 0.0;
    for (int i = tid; i < 2048; i += 256) { s += part[i]; ss += part[2048 + i]; }
    sd[tid] = s; ssd[tid] = ss;
    __syncthreads();
    for (int o = 128; o; o >>= 1) {
        if (tid < o) { sd[tid] += sd[tid + o]; ssd[tid] += ssd[tid + o]; }
        __syncthreads();
    }
    if (tid == 0) {
        double n = (double)TXT_N;
        double mu = sd[0] / n;
        double var = ssd[0] / n - mu * mu;
        stats[0] = (float)mu;
        stats[1] = (float)(1.0 / sqrt(var + 1e-6));
    }
}

__global__ void ln_apply(const float* __restrict__ x1, const float* __restrict__ x2,
                         const float* __restrict__ g, const float* __restrict__ bta,
                         const float* __restrict__ stats, float* __restrict__ out) {
    size_t i = (size_t)blockIdx.x * 256 + threadIdx.x;
    float mu = stats[0], r = stats[1];
    float v = x1[i] + x2[i];
    out[i] = (v - mu) * r * g[i] + bta[i];
}

__global__ void copy_img(const float* __restrict__ src, float* __restrict__ dst, int n) {
    int i = blockIdx.x * 256 + threadIdx.x;
    if (i < n) dst[i] = src[i];
}

// ---------------- launch ----------------
extern "C" void kernel_launch(void* const* d_in, const int* in_sizes, int n_in,
                              void* d_out, int out_size) {
    const float* text  = (const float*)d_in[0];
    const float* image = (const float*)d_in[1];
    const float* Wq = (const float*)d_in[2];
    const float* bq = (const float*)d_in[3];
    const float* Wk = (const float*)d_in[4];
    const float* bk = (const float*)d_in[5];
    const float* Wv = (const float*)d_in[6];
    const float* bv = (const float*)d_in[7];
    const float* W1 = (const float*)d_in[8];
    const float* b1 = (const float*)d_in[9];
    const float* W2 = (const float*)d_in[10];
    const float* b2 = (const float*)d_in[11];
    const float* gamma = (const float*)d_in[12];
    const float* beta  = (const float*)d_in[13];
    float* out = (float*)d_out;

    float *Q, *K, *V, *Vt, *SK, *O, *H, *M2, *FF, *att, *part, *stats, *P, *pp;
    cudaGetSymbolAddress((void**)&Q,  g_Q);
    cudaGetSymbolAddress((void**)&K,  g_K);
    cudaGetSymbolAddress((void**)&V,  g_V);
    cudaGetSymbolAddress((void**)&Vt, g_Vt);
    cudaGetSymbolAddress((void**)&SK, g_SK);
    cudaGetSymbolAddress((void**)&O,  g_O);
    cudaGetSymbolAddress((void**)&H,  g_H);
    cudaGetSymbolAddress((void**)&M2, g_M2);
    cudaGetSymbolAddress((void**)&FF, g_FF);
    cudaGetSymbolAddress((void**)&att, g_att);
    cudaGetSymbolAddress((void**)&part, g_part);
    cudaGetSymbolAddress((void**)&stats, g_stats);
    cudaGetSymbolAddress((void**)&P,  g_P);
    cudaGetSymbolAddress((void**)&pp, g_pp);

    static int smem_set = 0;
    if (!smem_set) {
        cudaFuncSetAttribute(tc_gemm, cudaFuncAttributeMaxDynamicSharedMemorySize, GEMM_SMEM);
        smem_set = 1;
    }

    // sparse-softmax coefficients
    double e = exp(1.0);
    float A[6], Bc[6];
    for (int n = 3; n <= 5; n++) {
        double Z = n * e + (double)(SEQ - n);
        A[n]  = (float)(e / Z);
        Bc[n] = (float)(1.0 / Z);
    }

    // QKV projections: [16384,256] = text @ W^T + bias
    tc_gemm<<<dim3(2, 128, 1), 256, GEMM_SMEM>>>(text, Wq, Q, NTOK, DIM, DIM, 0, 0, 0, 1.f, bq, 0);
    tc_gemm<<<dim3(2, 128, 1), 256, GEMM_SMEM>>>(text, Wk, K, NTOK, DIM, DIM, 0, 0, 0, 1.f, bk, 0);
    tc_gemm<<<dim3(2, 128, 1), 256, GEMM_SMEM>>>(text, Wv, V, NTOK, DIM, DIM, 0, 0, 0, 1.f, bv, 0);

    transpose_v<<<dim3(128, 8, BATCH), dim3(32, 8)>>>(V, Vt);

    // analytic sparse @ K
    prefix_partial<<<dim3(16, BATCH), 256>>>(K, pp);
    prefix_combine<<<BATCH, 256>>>(K, pp, P);
    sk_kernel<<<dim3(SEQ, BATCH), 256>>>(K, P, SK, A[3], Bc[3], A[4], Bc[4], A[5], Bc[5]);

    // att = Q @ SK^T / 16 (batched)
    tc_gemm<<<dim3(32, 32, BATCH), 256, GEMM_SMEM>>>(Q, SK, att, SEQ, SEQ, DIM,
        (long long)SEQ * DIM, (long long)SEQ * DIM, (long long)SEQ * SEQ, 0.0625f, nullptr, 0);
    softmax_rows<<<NTOK, 256>>>(att);

    // O = att @ Vt^T (batched)
    tc_gemm<<<dim3(2, 32, BATCH), 256, GEMM_SMEM>>>(att, Vt, O, SEQ, DIM, SEQ,
        (long long)SEQ * SEQ, (long long)SEQ * DIM, (long long)SEQ * DIM, 1.f, nullptr, 0);

    // LN1 over full tensor of (O + text) -> H
    ln_partial<<<2048, 256>>>(O, text, part);
    ln_combine<<<1, 256>>>(part, stats);
    ln_apply<<<NTOK, 256>>>(O, text, gamma, beta, stats, H);

    // MLP
    tc_gemm<<<dim3(8, 128, 1), 256, GEMM_SMEM>>>(H, W1, FF, NTOK, DFF, DIM, 0, 0, 0, 1.f, b1, 1);
    tc_gemm<<<dim3(2, 128, 1), 256, GEMM_SMEM>>>(FF, W2, M2, NTOK, DIM, DFF, 0, 0, 0, 1.f, b2, 0);

    // LN2 over full tensor of (M2 + text) -> out
    ln_partial<<<2048, 256>>>(M2, text, part);
    ln_combine<<<1, 256>>>(part, stats);
    ln_apply<<<NTOK, 256>>>(M2, text, gamma, beta, stats, out);

    // image passthrough
    if (out_size >= (int)TXT_N + IMG_N) {
        copy_img<<<(IMG_N + 255) / 256, 256>>>(image, out + TXT_N, IMG_N);
    }
}

// round 5
// speedup vs baseline: 3.0017x; 1.1480x over previous
#include <cuda_runtime.h>
#include <math.h>
#include <stdint.h>

// ---------------- problem constants ----------------
constexpr int BATCH = 4;
constexpr int SEQ   = 4096;
constexpr int DIM   = 256;
constexpr int DFF   = 1024;
constexpr int NTOK  = BATCH * SEQ;                 // 16384
constexpr size_t TXT_N = (size_t)NTOK * DIM;       // 4,194,304
constexpr int IMG_N = BATCH * 196 * DIM;           // 200,704

// ---------------- scratch (device globals; no allocs allowed) ----------------
__device__ float g_Q [4194304];
__device__ float g_K [4194304];
__device__ float g_V [4194304];
__device__ float g_Vt[4194304];
__device__ float g_SK[4194304];
__device__ float g_O [4194304];
__device__ float g_H [4194304];
__device__ float g_M2[4194304];
__device__ float g_FF[16777216];                   // [16384, 1024]
__device__ float g_part[4096];
__device__ float g_stats[2];
__device__ float g_P [BATCH * 4 * DIM];
__device__ float g_pp[BATCH * 16 * DIM];

// ================= async copy helpers (baseline PTX, sm_80+) =================
__device__ __forceinline__ uint32_t smem_u32(const void* p) {
    uint32_t a;
    asm("{ .reg .u64 t; cvta.to.shared.u64 t, %1; cvt.u32.u64 %0, t; }" : "=r"(a) : "l"(p));
    return a;
}
#define CP16(dst, src) \
    asm volatile("cp.async.cg.shared.global [%0], [%1], 16;" :: "r"(dst), "l"(src))
#define CP_COMMIT() asm volatile("cp.async.commit_group;" ::: "memory")
#define CP_WAIT(n)  asm volatile("cp.async.wait_group %0;" :: "n"(n) : "memory")

// mma.sync m16n8k8 tf32 (row.col): D += A*B
__device__ __forceinline__ void mma8(float* c, uint32_t a0, uint32_t a1,
                                     uint32_t a2, uint32_t a3, uint32_t b0, uint32_t b1) {
    asm volatile(
        "mma.sync.aligned.m16n8k8.row.col.f32.tf32.tf32.f32 "
        "{%0,%1,%2,%3}, {%4,%5,%6,%7}, {%8,%9}, {%0,%1,%2,%3};\n"
        : "+f"(c[0]), "+f"(c[1]), "+f"(c[2]), "+f"(c[3])
        : "r"(a0), "r"(a1), "r"(a2), "r"(a3), "r"(b0), "r"(b1));
}

// ================= tf32 tensor-core GEMM: C = alpha*A@B^T (+bias)(+relu) ======
constexpr int TCBM = 128, TCBN = 128, TCBK = 32;
constexpr int ASTRIDE = 36;
constexpr int STAGE_BYTES = 128 * ASTRIDE * 4;      // 18432
constexpr int GEMM_SMEM = 4 * STAGE_BYTES;          // 73728

__device__ __forceinline__ void load_stage_tc(
    uint32_t smA, uint32_t smB,
    const float* __restrict__ Ab, const float* __restrict__ Bb,
    int K, int k0, int tid)
{
#pragma unroll
    for (int it = 0; it < 4; it++) {
        int idx = tid + it * 256;
        int row = idx >> 3, seg = idx & 7;
        CP16(smA + (uint32_t)(row * ASTRIDE + seg * 4) * 4,
             Ab + (size_t)row * K + k0 + seg * 4);
    }
#pragma unroll
    for (int it = 0; it < 4; it++) {
        int idx = tid + it * 256;
        int row = idx >> 3, seg = idx & 7;
        CP16(smB + (uint32_t)(row * ASTRIDE + seg * 4) * 4,
             Bb + (size_t)row * K + k0 + seg * 4);
    }
}

__global__ void __launch_bounds__(256) tc_gemm(
    const float* __restrict__ A, const float* __restrict__ B, float* __restrict__ C,
    int M, int N, int K, long long sA, long long sB, long long sC,
    float alpha, const float* __restrict__ bias, int relu)
{
    extern __shared__ char smem[];
    const int tid = threadIdx.x;
    const int wid = tid >> 5, lane = tid & 31;
    const int wm = wid & 3, wn = wid >> 2;
    const int g = lane >> 2;
    const int tg = lane & 3;
    const int t2 = tg << 1;
    const int bx = blockIdx.x, by = blockIdx.y, bz = blockIdx.z;
    const int m0 = by * TCBM, n0 = bx * TCBN;
    const float* Ab = A + (size_t)bz * sA + (size_t)m0 * K;
    const float* Bb = B + (size_t)bz * sB + (size_t)n0 * K;
    float*       Cb = C + (size_t)bz * sC;

    const uint32_t sbase = smem_u32(smem);
    const uint32_t smA[2] = { sbase, sbase + STAGE_BYTES };
    const uint32_t smB[2] = { sbase + 2 * STAGE_BYTES, sbase + 3 * STAGE_BYTES };

    float acc[2][8][4];
#pragma unroll
    for (int i = 0; i < 2; i++)
#pragma unroll
        for (int j = 0; j < 8; j++)
#pragma unroll
            for (int v = 0; v < 4; v++) acc[i][j][v] = 0.f;

    const int KT = K / TCBK;
    load_stage_tc(smA[0], smB[0], Ab, Bb, K, 0, tid);
    CP_COMMIT();

    for (int kt = 0; kt < KT; kt++) {
        const int cur = kt & 1;
        if (kt + 1 < KT) {
            load_stage_tc(smA[cur ^ 1], smB[cur ^ 1], Ab, Bb, K, (kt + 1) * TCBK, tid);
            CP_COMMIT();
            CP_WAIT(1);
        } else {
            CP_WAIT(0);
        }
        __syncthreads();

        const float* As = (const float*)(smem + (size_t)cur * STAGE_BYTES);
        const float* Bs = (const float*)(smem + (size_t)(2 + cur) * STAGE_BYTES);
#pragma unroll
        for (int step = 0; step < 4; step++) {
            const int k0 = step * 8;
            uint32_t afr[2][4];
#pragma unroll
            for (int i = 0; i < 2; i++) {
                int r = wm * 32 + i * 16 + g;
                afr[i][0] = __float_as_uint(As[r * ASTRIDE + k0 + tg]);
                afr[i][1] = __float_as_uint(As[(r + 8) * ASTRIDE + k0 + tg]);
                afr[i][2] = __float_as_uint(As[r * ASTRIDE + k0 + tg + 4]);
                afr[i][3] = __float_as_uint(As[(r + 8) * ASTRIDE + k0 + tg + 4]);
            }
#pragma unroll
            for (int j = 0; j < 8; j++) {
                int n = wn * 64 + j * 8 + g;
                uint32_t b0 = __float_as_uint(Bs[n * ASTRIDE + k0 + tg]);
                uint32_t b1 = __float_as_uint(Bs[n * ASTRIDE + k0 + tg + 4]);
#pragma unroll
                for (int i = 0; i < 2; i++) {
                    mma8(acc[i][j], afr[i][0], afr[i][1], afr[i][2], afr[i][3], b0, b1);
                }
            }
        }
        __syncthreads();
    }

#pragma unroll
    for (int i = 0; i < 2; i++) {
        int r = m0 + wm * 32 + i * 16 + g;
        float* crow0 = Cb + (size_t)r * N;
        float* crow1 = crow0 + (size_t)8 * N;
#pragma unroll
        for (int j = 0; j < 8; j++) {
            int c = n0 + wn * 64 + j * 8 + t2;
            float2 v0, v1;
            v0.x = acc[i][j][0] * alpha; v0.y = acc[i][j][1] * alpha;
            v1.x = acc[i][j][2] * alpha; v1.y = acc[i][j][3] * alpha;
            if (bias) {
                float bb0 = __ldg(bias + c), bb1 = __ldg(bias + c + 1);
                v0.x += bb0; v0.y += bb1;
                v1.x += bb0; v1.y += bb1;
            }
            if (relu) {
                v0.x = fmaxf(v0.x, 0.f); v0.y = fmaxf(v0.y, 0.f);
                v1.x = fmaxf(v1.x, 0.f); v1.y = fmaxf(v1.y, 0.f);
            }
            *(float2*)(crow0 + c) = v0;
            *(float2*)(crow1 + c) = v1;
        }
    }
}

// ================= fused flash attention (no max-rescale; scores tiny) =======
// O[b, q, :] = exp(Q@SK^T/16) @ V / rowsum.  Per CTA: 64 q-rows, stream 128-row
// s-tiles; SK in 32-k chunks, P via smem, Vt in 32-k chunks. 8 warps = 2m x 4n.
constexpr int FQT = 64;                              // q rows per CTA
constexpr int FST = 128;                             // s tile
constexpr int QSTR = 260;                            // Q smem stride (floats)
constexpr int FSTR = 36;                             // chunk smem stride
constexpr int PSTR = 132;                            // P smem stride
constexpr int OFF_Q  = 0;                            // 64*260*4   = 66560
constexpr int OFF_SK = 66560;                        // 2*128*36*4 = 36864
constexpr int OFF_P  = 103424;                       // 64*132*4   = 33792
constexpr int OFF_V  = 137216;                       // 2*256*36*4 = 73728
constexpr int OFF_RS = 210944;                       // 64*4       = 256
constexpr int FLASH_SMEM = 211200;

__device__ __forceinline__ void f_load_sk(uint32_t dst, const float* __restrict__ SKb,
                                          int s0, int kc, int tid) {
#pragma unroll
    for (int it = 0; it < 4; it++) {
        int idx = tid + it * 256;                    // 0..1023
        int row = idx >> 3, seg = idx & 7;
        CP16(dst + (uint32_t)(row * FSTR + seg * 4) * 4,
             SKb + (size_t)(s0 + row) * DIM + kc * 32 + seg * 4);
    }
}
__device__ __forceinline__ void f_load_v(uint32_t dst, const float* __restrict__ Vtb,
                                         int s0, int vc, int tid) {
#pragma unroll
    for (int it = 0; it < 8; it++) {
        int idx = tid + it * 256;                    // 0..2047
        int row = idx >> 3, seg = idx & 7;
        CP16(dst + (uint32_t)(row * FSTR + seg * 4) * 4,
             Vtb + (size_t)row * SEQ + s0 + vc * 32 + seg * 4);
    }
}

__global__ void __launch_bounds__(256, 1) flash_attn(
    const float* __restrict__ Q, const float* __restrict__ SK,
    const float* __restrict__ Vt, float* __restrict__ O)
{
    extern __shared__ char smem[];
    const int tid = threadIdx.x;
    const int wid = tid >> 5, lane = tid & 31;
    const int wm = wid & 1, wn = wid >> 1;           // 2m x 4n
    const int g = lane >> 2, tg = lane & 3, t2 = tg << 1;
    const int qbase = blockIdx.x * FQT;
    const int b = blockIdx.y;

    const float* Qb  = Q  + (size_t)b * SEQ * DIM;
    const float* SKb = SK + (size_t)b * SEQ * DIM;
    const float* Vtb = Vt + (size_t)b * SEQ * DIM;
    float*       Ob  = O  + (size_t)b * SEQ * DIM;

    const uint32_t sbase = smem_u32(smem);
    const uint32_t smQ = sbase + OFF_Q;
    const uint32_t smSK[2] = { sbase + OFF_SK, sbase + OFF_SK + FST * FSTR * 4 };
    const uint32_t smV[2]  = { sbase + OFF_V,  sbase + OFF_V  + DIM * FSTR * 4 };
    float* Qs = (float*)(smem + OFF_Q);
    float* Ps = (float*)(smem + OFF_P);
    float* rowsumS = (float*)(smem + OFF_RS);

    if (tid < FQT) rowsumS[tid] = 0.f;

    // load Q tile (64 x 256)
#pragma unroll
    for (int it = 0; it < 16; it++) {
        int idx = tid + it * 256;                    // 0..4095
        int row = idx >> 6, seg = idx & 63;
        CP16(smQ + (uint32_t)(row * QSTR + seg * 4) * 4,
             Qb + (size_t)(qbase + row) * DIM + seg * 4);
    }
    CP_COMMIT();
    f_load_sk(smSK[0], SKb, 0, 0, tid);
    CP_COMMIT();

    float Oacc[2][8][4];
#pragma unroll
    for (int i = 0; i < 2; i++)
#pragma unroll
        for (int j = 0; j < 8; j++)
#pragma unroll
            for (int v = 0; v < 4; v++) Oacc[i][j][v] = 0.f;
    float rsum[2][2] = {{0.f, 0.f}, {0.f, 0.f}};

    constexpr float EXPC = 0.09016844f;              // log2(e)/16

    for (int t = 0; t < 32; t++) {
        const int s0 = t * FST;
        float Sacc[2][4][4];
#pragma unroll
        for (int i = 0; i < 2; i++)
#pragma unroll
            for (int j = 0; j < 4; j++)
#pragma unroll
                for (int v = 0; v < 4; v++) Sacc[i][j][v] = 0.f;

        // ---- S = Q @ SK_tile^T over k=256 in 8 chunks ----
        for (int c = 0; c < 8; c++) {
            CP_WAIT(0);
            __syncthreads();
            if (c < 7) { f_load_sk(smSK[(c + 1) & 1], SKb, s0, c + 1, tid); CP_COMMIT(); }
            else       { f_load_v(smV[0], Vtb, s0, 0, tid); CP_COMMIT(); }
            const float* Sks = (const float*)(smem + OFF_SK + (c & 1) * FST * FSTR * 4);
#pragma unroll
            for (int step = 0; step < 4; step++) {
                const int qk = c * 32 + step * 8;
                const int k0 = step * 8;
                uint32_t afr[2][4];
#pragma unroll
                for (int i = 0; i < 2; i++) {
                    int r = wm * 32 + i * 16 + g;
                    afr[i][0] = __float_as_uint(Qs[r * QSTR + qk + tg]);
                    afr[i][1] = __float_as_uint(Qs[(r + 8) * QSTR + qk + tg]);
                    afr[i][2] = __float_as_uint(Qs[r * QSTR + qk + tg + 4]);
                    afr[i][3] = __float_as_uint(Qs[(r + 8) * QSTR + qk + tg + 4]);
                }
#pragma unroll
                for (int j = 0; j < 4; j++) {
                    int n = wn * 32 + j * 8 + g;
                    uint32_t b0 = __float_as_uint(Sks[n * FSTR + k0 + tg]);
                    uint32_t b1 = __float_as_uint(Sks[n * FSTR + k0 + tg + 4]);
#pragma unroll
                    for (int i = 0; i < 2; i++)
                        mma8(Sacc[i][j], afr[i][0], afr[i][1], afr[i][2], afr[i][3], b0, b1);
                }
            }
        }

        // ---- P = exp(S/16); accumulate rowsums; stage P in smem ----
#pragma unroll
        for (int i = 0; i < 2; i++) {
            int r = wm * 32 + i * 16 + g;
#pragma unroll
            for (int j = 0; j < 4; j++) {
                int col = wn * 32 + j * 8 + t2;
                float p0 = exp2f(Sacc[i][j][0] * EXPC);
                float p1 = exp2f(Sacc[i][j][1] * EXPC);
                float p2 = exp2f(Sacc[i][j][2] * EXPC);
                float p3 = exp2f(Sacc[i][j][3] * EXPC);
                rsum[i][0] += p0 + p1;
                rsum[i][1] += p2 + p3;
                *(float2*)&Ps[r * PSTR + col]       = make_float2(p0, p1);
                *(float2*)&Ps[(r + 8) * PSTR + col] = make_float2(p2, p3);
            }
        }

        // ---- O += P @ V_tile over k=128 in 4 chunks ----
        for (int v = 0; v < 4; v++) {
            CP_WAIT(0);
            __syncthreads();                          // V chunk ready + P visible (v==0)
            if (v < 3)       { f_load_v(smV[(v + 1) & 1], Vtb, s0, v + 1, tid); CP_COMMIT(); }
            else if (t < 31) { f_load_sk(smSK[0], SKb, s0 + FST, 0, tid); CP_COMMIT(); }
            const float* Vs = (const float*)(smem + OFF_V + (v & 1) * DIM * FSTR * 4);
#pragma unroll
            for (int step = 0; step < 4; step++) {
                const int pk = v * 32 + step * 8;
                const int k0 = step * 8;
                uint32_t afr[2][4];
#pragma unroll
                for (int i = 0; i < 2; i++) {
                    int r = wm * 32 + i * 16 + g;
                    afr[i][0] = __float_as_uint(Ps[r * PSTR + pk + tg]);
                    afr[i][1] = __float_as_uint(Ps[(r + 8) * PSTR + pk + tg]);
                    afr[i][2] = __float_as_uint(Ps[r * PSTR + pk + tg + 4]);
                    afr[i][3] = __float_as_uint(Ps[(r + 8) * PSTR + pk + tg + 4]);
                }
#pragma unroll
                for (int j = 0; j < 8; j++) {
                    int n = wn * 64 + j * 8 + g;
                    uint32_t b0 = __float_as_uint(Vs[n * FSTR + k0 + tg]);
                    uint32_t b1 = __float_as_uint(Vs[n * FSTR + k0 + tg + 4]);
#pragma unroll
                    for (int i = 0; i < 2; i++)
                        mma8(Oacc[i][j], afr[i][0], afr[i][1], afr[i][2], afr[i][3], b0, b1);
                }
            }
            __syncthreads();                          // done reading before next P write / V overwrite
        }
    }

    // ---- rowsum reduce: across tg lanes then across wn warps ----
#pragma unroll
    for (int i = 0; i < 2; i++)
#pragma unroll
        for (int h = 0; h < 2; h++) {
            float v = rsum[i][h];
            v += __shfl_xor_sync(0xffffffffu, v, 1);
            v += __shfl_xor_sync(0xffffffffu, v, 2);
            rsum[i][h] = v;
        }
    if (tg == 0) {
#pragma unroll
        for (int i = 0; i < 2; i++) {
            atomicAdd(&rowsumS[wm * 32 + i * 16 + g], rsum[i][0]);
            atomicAdd(&rowsumS[wm * 32 + i * 16 + g + 8], rsum[i][1]);
        }
    }
    __syncthreads();

    // ---- normalize + write O ----
#pragma unroll
    for (int i = 0; i < 2; i++) {
        int r = wm * 32 + i * 16 + g;
        float inv0 = 1.f / rowsumS[r];
        float inv1 = 1.f / rowsumS[r + 8];
        float* orow0 = Ob + (size_t)(qbase + r) * DIM;
        float* orow1 = orow0 + (size_t)8 * DIM;
#pragma unroll
        for (int j = 0; j < 8; j++) {
            int c = wn * 64 + j * 8 + t2;
            *(float2*)(orow0 + c) = make_float2(Oacc[i][j][0] * inv0, Oacc[i][j][1] * inv0);
            *(float2*)(orow1 + c) = make_float2(Oacc[i][j][2] * inv1, Oacc[i][j][3] * inv1);
        }
    }
}

// ---------------- V transpose: Vt[b,d,s] = V[b,s,d] ----------------
__global__ void transpose_v(const float* __restrict__ V, float* __restrict__ Vt) {
    __shared__ float t[32][33];
    int b = blockIdx.z;
    int s0 = blockIdx.x * 32, d0 = blockIdx.y * 32;
    const float* Vb = V + (size_t)b * SEQ * DIM;
    float* Vtb = Vt + (size_t)b * SEQ * DIM;
    int x = threadIdx.x, y = threadIdx.y;
#pragma unroll
    for (int i = 0; i < 32; i += 8)
        t[y + i][x] = Vb[(size_t)(s0 + y + i) * DIM + d0 + x];
    __syncthreads();
#pragma unroll
    for (int i = 0; i < 32; i += 8)
        Vtb[(size_t)(d0 + y + i) * SEQ + s0 + x] = t[x][y + i];
}

// ---------------- prefix sums of K rows (analytic sparse@K) ----------------
__global__ void prefix_partial(const float* __restrict__ Kmat, float* __restrict__ pp) {
    int ch = blockIdx.x, b = blockIdx.y, d = threadIdx.x;
    int s0 = ch * 128;
    int s1 = min(s0 + 128, 2047);
    const float* Kb = Kmat + (size_t)b * SEQ * DIM;
    float s = 0.f;
    for (int ss = s0; ss < s1; ss++) s += Kb[(size_t)ss * DIM + d];
    pp[((size_t)b * 16 + ch) * DIM + d] = s;
}

__global__ void prefix_combine(const float* __restrict__ Kmat,
                               const float* __restrict__ pp, float* __restrict__ P) {
    int b = blockIdx.x, d = threadIdx.x;
    const float* Kb = Kmat + (size_t)b * SEQ * DIM;
    float s = 0.f;
    for (int ch = 0; ch < 16; ch++) s += pp[((size_t)b * 16 + ch) * DIM + d];
    float p2047 = s;
    float p2048 = p2047 + Kb[(size_t)2047 * DIM + d];
    float p2049 = p2048 + Kb[(size_t)2048 * DIM + d];
    float p2052 = p2049 + Kb[(size_t)2049 * DIM + d]
                        + Kb[(size_t)2050 * DIM + d]
                        + Kb[(size_t)2051 * DIM + d];
    float* Pb = P + (size_t)b * 4 * DIM;
    Pb[0 * DIM + d] = p2047;
    Pb[1 * DIM + d] = p2048;
    Pb[2 * DIM + d] = p2049;
    Pb[3 * DIM + d] = p2052;
}

__global__ void sk_kernel(const float* __restrict__ Kmat, const float* __restrict__ P,
                          float* __restrict__ SK,
                          float A3, float B3, float A4, float B4, float A5, float B5) {
    int i = blockIdx.x, b = blockIdx.y, d = threadIdx.x;
    const float* Kb = Kmat + (size_t)b * SEQ * DIM;
    int lo = max(i - 2, 0), hi = min(i + 2, SEQ - 1);
    int n = hi - lo + 1;
    float band = 0.f;
    for (int j = lo; j <= hi; j++) band += Kb[(size_t)j * DIM + d];
    const float* Pb = P + (size_t)b * 4 * DIM;
    float off;
    if (i <= 2048) off = Pb[3 * DIM + d] - band;
    else           off = Pb[(5 - n) * DIM + d];
    float a, bb;
    if (n == 5)      { a = A5; bb = B5; }
    else if (n == 4) { a = A4; bb = B4; }
    else             { a = A3; bb = B3; }
    SK[((size_t)b * SEQ + i) * DIM + d] = a * band + bb * off;
}

// ---------------- full-tensor LayerNorm ----------------
__global__ void ln_partial(const float* __restrict__ x1, const float* __restrict__ x2,
                           float* __restrict__ part) {
    int tid = threadIdx.x, bid = blockIdx.x;
    float s = 0.f, ss = 0.f;
    for (size_t i = (size_t)bid * 256 + tid; i < TXT_N; i += (size_t)2048 * 256) {
        float v = x1[i] + x2[i];
        s += v;
        ss = fmaf(v, v, ss);
    }
    __shared__ float rs[256], rss[256];
    rs[tid] = s; rss[tid] = ss;
    __syncthreads();
    for (int o = 128; o; o >>= 1) {
        if (tid < o) { rs[tid] += rs[tid + o]; rss[tid] += rss[tid + o]; }
        __syncthreads();
    }
    if (tid == 0) { part[bid] = rs[0]; part[2048 + bid] = rss[0]; }
}

__global__ void ln_combine(const float* __restrict__ part, float* __restrict__ stats) {
    __shared__ double sd[256], ssd[256];
    int tid = threadIdx.x;
    double s = 0.0, ss = 0.0;
    for (int i = tid; i < 2048; i += 256) { s += part[i]; ss += part[2048 + i]; }
    sd[tid] = s; ssd[tid] = ss;
    __syncthreads();
    for (int o = 128; o; o >>= 1) {
        if (tid < o) { sd[tid] += sd[tid + o]; ssd[tid] += ssd[tid + o]; }
        __syncthreads();
    }
    if (tid == 0) {
        double n = (double)TXT_N;
        double mu = sd[0] / n;
        double var = ssd[0] / n - mu * mu;
        stats[0] = (float)mu;
        stats[1] = (float)(1.0 / sqrt(var + 1e-6));
    }
}

__global__ void ln_apply(const float* __restrict__ x1, const float* __restrict__ x2,
                         const float* __restrict__ g, const float* __restrict__ bta,
                         const float* __restrict__ stats, float* __restrict__ out) {
    size_t i = (size_t)blockIdx.x * 256 + threadIdx.x;
    float mu = stats[0], r = stats[1];
    float v = x1[i] + x2[i];
    out[i] = (v - mu) * r * g[i] + bta[i];
}

__global__ void copy_img(const float* __restrict__ src, float* __restrict__ dst, int n) {
    int i = blockIdx.x * 256 + threadIdx.x;
    if (i < n) dst[i] = src[i];
}

// ---------------- launch ----------------
extern "C" void kernel_launch(void* const* d_in, const int* in_sizes, int n_in,
                              void* d_out, int out_size) {
    const float* text  = (const float*)d_in[0];
    const float* image = (const float*)d_in[1];
    const float* Wq = (const float*)d_in[2];
    const float* bq = (const float*)d_in[3];
    const float* Wk = (const float*)d_in[4];
    const float* bk = (const float*)d_in[5];
    const float* Wv = (const float*)d_in[6];
    const float* bv = (const float*)d_in[7];
    const float* W1 = (const float*)d_in[8];
    const float* b1 = (const float*)d_in[9];
    const float* W2 = (const float*)d_in[10];
    const float* b2 = (const float*)d_in[11];
    const float* gamma = (const float*)d_in[12];
    const float* beta  = (const float*)d_in[13];
    float* out = (float*)d_out;

    float *Q, *K, *V, *Vt, *SK, *O, *H, *M2, *FF, *part, *stats, *P, *pp;
    cudaGetSymbolAddress((void**)&Q,  g_Q);
    cudaGetSymbolAddress((void**)&K,  g_K);
    cudaGetSymbolAddress((void**)&V,  g_V);
    cudaGetSymbolAddress((void**)&Vt, g_Vt);
    cudaGetSymbolAddress((void**)&SK, g_SK);
    cudaGetSymbolAddress((void**)&O,  g_O);
    cudaGetSymbolAddress((void**)&H,  g_H);
    cudaGetSymbolAddress((void**)&M2, g_M2);
    cudaGetSymbolAddress((void**)&FF, g_FF);
    cudaGetSymbolAddress((void**)&part, g_part);
    cudaGetSymbolAddress((void**)&stats, g_stats);
    cudaGetSymbolAddress((void**)&P,  g_P);
    cudaGetSymbolAddress((void**)&pp, g_pp);

    static int smem_set = 0;
    if (!smem_set) {
        cudaFuncSetAttribute(tc_gemm, cudaFuncAttributeMaxDynamicSharedMemorySize, GEMM_SMEM);
        cudaFuncSetAttribute(flash_attn, cudaFuncAttributeMaxDynamicSharedMemorySize, FLASH_SMEM);
        smem_set = 1;
    }

    // sparse-softmax coefficients
    double e = exp(1.0);
    float A[6], Bc[6];
    for (int n = 3; n <= 5; n++) {
        double Z = n * e + (double)(SEQ - n);
        A[n]  = (float)(e / Z);
        Bc[n] = (float)(1.0 / Z);
    }

    // QKV projections
    tc_gemm<<<dim3(2, 128, 1), 256, GEMM_SMEM>>>(text, Wq, Q, NTOK, DIM, DIM, 0, 0, 0, 1.f, bq, 0);
    tc_gemm<<<dim3(2, 128, 1), 256, GEMM_SMEM>>>(text, Wk, K, NTOK, DIM, DIM, 0, 0, 0, 1.f, bk, 0);
    tc_gemm<<<dim3(2, 128, 1), 256, GEMM_SMEM>>>(text, Wv, V, NTOK, DIM, DIM, 0, 0, 0, 1.f, bv, 0);

    transpose_v<<<dim3(128, 8, BATCH), dim3(32, 8)>>>(V, Vt);

    // analytic sparse @ K
    prefix_partial<<<dim3(16, BATCH), 256>>>(K, pp);
    prefix_combine<<<BATCH, 256>>>(K, pp, P);
    sk_kernel<<<dim3(SEQ, BATCH), 256>>>(K, P, SK, A[3], Bc[3], A[4], Bc[4], A[5], Bc[5]);

    // fused attention: O = softmax(Q@SK^T/16) @ V
    flash_attn<<<dim3(SEQ / FQT, BATCH), 256, FLASH_SMEM>>>(Q, SK, Vt, O);

    // LN1 over full tensor of (O + text) -> H
    ln_partial<<<2048, 256>>>(O, text, part);
    ln_combine<<<1, 256>>>(part, stats);
    ln_apply<<<NTOK, 256>>>(O, text, gamma, beta, stats, H);

    // MLP
    tc_gemm<<<dim3(8, 128, 1), 256, GEMM_SMEM>>>(H, W1, FF, NTOK, DFF, DIM, 0, 0, 0, 1.f, b1, 1);
    tc_gemm<<<dim3(2, 128, 1), 256, GEMM_SMEM>>>(FF, W2, M2, NTOK, DIM, DFF, 0, 0, 0, 1.f, b2, 0);

    // LN2 over full tensor of (M2 + text) -> out
    ln_partial<<<2048, 256>>>(M2, text, part);
    ln_combine<<<1, 256>>>(part, stats);
    ln_apply<<<NTOK, 256>>>(M2, text, gamma, beta, stats, out);

    // image passthrough
    if (out_size >= (int)TXT_N + IMG_N) {
        copy_img<<<(IMG_N + 255) / 256, 256>>>(image, out + TXT_N, IMG_N);
    }
}

// round 6
// speedup vs baseline: 3.3408x; 1.1130x over previous
#include <cuda_runtime.h>
#include <math.h>
#include <stdint.h>

// ---------------- problem constants ----------------
constexpr int BATCH = 4;
constexpr int SEQ   = 4096;
constexpr int DIM   = 256;
constexpr int DFF   = 1024;
constexpr int NTOK  = BATCH * SEQ;                 // 16384
constexpr size_t TXT_N = (size_t)NTOK * DIM;       // 4,194,304
constexpr int IMG_N = BATCH * 196 * DIM;           // 200,704

// ---------------- scratch (device globals; no allocs allowed) ----------------
__device__ float g_Q [4194304];
__device__ float g_K [4194304];
__device__ float g_V [4194304];
__device__ float g_Vt[4194304];
__device__ float g_SK[4194304];
__device__ float g_O [4194304];
__device__ float g_H [4194304];
__device__ float g_M2[4194304];
__device__ float g_FF[16777216];                   // [16384, 1024]
__device__ float g_part[4096];
__device__ float g_stats[2];
__device__ float g_P [BATCH * 4 * DIM];
__device__ float g_pp[BATCH * 16 * DIM];

// ================= async copy helpers (baseline PTX, sm_80+) =================
__device__ __forceinline__ uint32_t smem_u32(const void* p) {
    uint32_t a;
    asm("{ .reg .u64 t; cvta.to.shared.u64 t, %1; cvt.u32.u64 %0, t; }" : "=r"(a) : "l"(p));
    return a;
}
#define CP16(dst, src) \
    asm volatile("cp.async.cg.shared.global [%0], [%1], 16;" :: "r"(dst), "l"(src))
#define CP_COMMIT() asm volatile("cp.async.commit_group;" ::: "memory")
#define CP_WAIT(n)  asm volatile("cp.async.wait_group %0;" :: "n"(n) : "memory")

// mma.sync m16n8k8 tf32 (row.col): D += A*B
__device__ __forceinline__ void mma8(float* c, uint32_t a0, uint32_t a1,
                                     uint32_t a2, uint32_t a3, uint32_t b0, uint32_t b1) {
    asm volatile(
        "mma.sync.aligned.m16n8k8.row.col.f32.tf32.tf32.f32 "
        "{%0,%1,%2,%3}, {%4,%5,%6,%7}, {%8,%9}, {%0,%1,%2,%3};\n"
        : "+f"(c[0]), "+f"(c[1]), "+f"(c[2]), "+f"(c[3])
        : "r"(a0), "r"(a1), "r"(a2), "r"(a3), "r"(b0), "r"(b1));
}

// ================= tf32 tensor-core GEMM: C = alpha*A@B^T (+bias)(+relu) ======
constexpr int TCBM = 128, TCBN = 128, TCBK = 32;
constexpr int ASTRIDE = 36;
constexpr int STAGE_BYTES = 128 * ASTRIDE * 4;      // 18432
constexpr int GEMM_SMEM = 4 * STAGE_BYTES;          // 73728

__device__ __forceinline__ void load_stage_tc(
    uint32_t smA, uint32_t smB,
    const float* __restrict__ Ab, const float* __restrict__ Bb,
    int K, int k0, int tid)
{
#pragma unroll
    for (int it = 0; it < 4; it++) {
        int idx = tid + it * 256;
        int row = idx >> 3, seg = idx & 7;
        CP16(smA + (uint32_t)(row * ASTRIDE + seg * 4) * 4,
             Ab + (size_t)row * K + k0 + seg * 4);
    }
#pragma unroll
    for (int it = 0; it < 4; it++) {
        int idx = tid + it * 256;
        int row = idx >> 3, seg = idx & 7;
        CP16(smB + (uint32_t)(row * ASTRIDE + seg * 4) * 4,
             Bb + (size_t)row * K + k0 + seg * 4);
    }
}

__global__ void __launch_bounds__(256) tc_gemm(
    const float* __restrict__ A, const float* __restrict__ B, float* __restrict__ C,
    int M, int N, int K, long long sA, long long sB, long long sC,
    float alpha, const float* __restrict__ bias, int relu)
{
    extern __shared__ char smem[];
    const int tid = threadIdx.x;
    const int wid = tid >> 5, lane = tid & 31;
    const int wm = wid & 3, wn = wid >> 2;
    const int g = lane >> 2;
    const int tg = lane & 3;
    const int t2 = tg << 1;
    const int bx = blockIdx.x, by = blockIdx.y, bz = blockIdx.z;
    const int m0 = by * TCBM, n0 = bx * TCBN;
    const float* Ab = A + (size_t)bz * sA + (size_t)m0 * K;
    const float* Bb = B + (size_t)bz * sB + (size_t)n0 * K;
    float*       Cb = C + (size_t)bz * sC;

    const uint32_t sbase = smem_u32(smem);
    const uint32_t smA[2] = { sbase, sbase + STAGE_BYTES };
    const uint32_t smB[2] = { sbase + 2 * STAGE_BYTES, sbase + 3 * STAGE_BYTES };

    float acc[2][8][4];
#pragma unroll
    for (int i = 0; i < 2; i++)
#pragma unroll
        for (int j = 0; j < 8; j++)
#pragma unroll
            for (int v = 0; v < 4; v++) acc[i][j][v] = 0.f;

    const int KT = K / TCBK;
    load_stage_tc(smA[0], smB[0], Ab, Bb, K, 0, tid);
    CP_COMMIT();

    for (int kt = 0; kt < KT; kt++) {
        const int cur = kt & 1;
        if (kt + 1 < KT) {
            load_stage_tc(smA[cur ^ 1], smB[cur ^ 1], Ab, Bb, K, (kt + 1) * TCBK, tid);
            CP_COMMIT();
            CP_WAIT(1);
        } else {
            CP_WAIT(0);
        }
        __syncthreads();

        const float* As = (const float*)(smem + (size_t)cur * STAGE_BYTES);
        const float* Bs = (const float*)(smem + (size_t)(2 + cur) * STAGE_BYTES);
#pragma unroll
        for (int step = 0; step < 4; step++) {
            const int k0 = step * 8;
            uint32_t afr[2][4];
#pragma unroll
            for (int i = 0; i < 2; i++) {
                int r = wm * 32 + i * 16 + g;
                afr[i][0] = __float_as_uint(As[r * ASTRIDE + k0 + tg]);
                afr[i][1] = __float_as_uint(As[(r + 8) * ASTRIDE + k0 + tg]);
                afr[i][2] = __float_as_uint(As[r * ASTRIDE + k0 + tg + 4]);
                afr[i][3] = __float_as_uint(As[(r + 8) * ASTRIDE + k0 + tg + 4]);
            }
#pragma unroll
            for (int j = 0; j < 8; j++) {
                int n = wn * 64 + j * 8 + g;
                uint32_t b0 = __float_as_uint(Bs[n * ASTRIDE + k0 + tg]);
                uint32_t b1 = __float_as_uint(Bs[n * ASTRIDE + k0 + tg + 4]);
#pragma unroll
                for (int i = 0; i < 2; i++) {
                    mma8(acc[i][j], afr[i][0], afr[i][1], afr[i][2], afr[i][3], b0, b1);
                }
            }
        }
        __syncthreads();
    }

#pragma unroll
    for (int i = 0; i < 2; i++) {
        int r = m0 + wm * 32 + i * 16 + g;
        float* crow0 = Cb + (size_t)r * N;
        float* crow1 = crow0 + (size_t)8 * N;
#pragma unroll
        for (int j = 0; j < 8; j++) {
            int c = n0 + wn * 64 + j * 8 + t2;
            float2 v0, v1;
            v0.x = acc[i][j][0] * alpha; v0.y = acc[i][j][1] * alpha;
            v1.x = acc[i][j][2] * alpha; v1.y = acc[i][j][3] * alpha;
            if (bias) {
                float bb0 = __ldg(bias + c), bb1 = __ldg(bias + c + 1);
                v0.x += bb0; v0.y += bb1;
                v1.x += bb0; v1.y += bb1;
            }
            if (relu) {
                v0.x = fmaxf(v0.x, 0.f); v0.y = fmaxf(v0.y, 0.f);
                v1.x = fmaxf(v1.x, 0.f); v1.y = fmaxf(v1.y, 0.f);
            }
            *(float2*)(crow0 + c) = v0;
            *(float2*)(crow1 + c) = v1;
        }
    }
}

// ================= fused flash attention v2: FQT=128, Q streamed ==============
// O[b,q,:] = exp(Q@SK^T/16) @ V / rowsum. Per CTA: 128 q-rows; per 128-s tile:
// stream (Q,SK) 32-k chunks (db), exp->P smem, stream Vt 32-s chunks (db).
// 8 warps = 2m x 4n. S warp tile 64x32, O warp tile 64x64.
constexpr int FQT = 128;
constexpr int FST = 128;
constexpr int FSTR = 36;
constexpr int PSTR = 132;
constexpr int CHUNK_B = 128 * FSTR * 4;              // 18432
constexpr int VCHUNK_B = 256 * FSTR * 4;             // 36864
constexpr int OFF_QC = 0;                            // 2 * 18432 = 36864
constexpr int OFF_SKC = 36864;                       // 2 * 18432 = 36864
constexpr int OFF_P  = 73728;                        // 128*132*4 = 67584
constexpr int OFF_V  = 141312;                       // 2 * 36864 = 73728
constexpr int OFF_RS = 215040;                       // 128*4     = 512
constexpr int FLASH_SMEM = 215552;

// load 128 rows x 32 k-cols from row-major [*, DIM] matrix
__device__ __forceinline__ void f_load_rk(uint32_t dst, const float* __restrict__ Mb,
                                          int r0, int kc, int tid) {
#pragma unroll
    for (int it = 0; it < 4; it++) {
        int idx = tid + it * 256;                    // 0..1023
        int row = idx >> 3, seg = idx & 7;
        CP16(dst + (uint32_t)(row * FSTR + seg * 4) * 4,
             Mb + (size_t)(r0 + row) * DIM + kc * 32 + seg * 4);
    }
}
// load 256 d-rows x 32 s-cols from Vt [DIM, SEQ]
__device__ __forceinline__ void f_load_v(uint32_t dst, const float* __restrict__ Vtb,
                                         int s0, int vc, int tid) {
#pragma unroll
    for (int it = 0; it < 8; it++) {
        int idx = tid + it * 256;                    // 0..2047
        int row = idx >> 3, seg = idx & 7;
        CP16(dst + (uint32_t)(row * FSTR + seg * 4) * 4,
             Vtb + (size_t)row * SEQ + s0 + vc * 32 + seg * 4);
    }
}

__global__ void __launch_bounds__(256, 1) flash_attn(
    const float* __restrict__ Q, const float* __restrict__ SK,
    const float* __restrict__ Vt, float* __restrict__ O)
{
    extern __shared__ char smem[];
    const int tid = threadIdx.x;
    const int wid = tid >> 5, lane = tid & 31;
    const int wm = wid & 1, wn = wid >> 1;           // 2m x 4n
    const int g = lane >> 2, tg = lane & 3, t2 = tg << 1;
    const int qbase = blockIdx.x * FQT;
    const int b = blockIdx.y;

    const float* Qb  = Q  + (size_t)b * SEQ * DIM;
    const float* SKb = SK + (size_t)b * SEQ * DIM;
    const float* Vtb = Vt + (size_t)b * SEQ * DIM;
    float*       Ob  = O  + (size_t)b * SEQ * DIM;

    const uint32_t sbase = smem_u32(smem);
    const uint32_t smQC[2]  = { sbase + OFF_QC,  sbase + OFF_QC  + CHUNK_B };
    const uint32_t smSKC[2] = { sbase + OFF_SKC, sbase + OFF_SKC + CHUNK_B };
    const uint32_t smV[2]   = { sbase + OFF_V,   sbase + OFF_V   + VCHUNK_B };
    float* Ps = (float*)(smem + OFF_P);
    float* rowsumS = (float*)(smem + OFF_RS);

    if (tid < FQT) rowsumS[tid] = 0.f;

    // prologue: group G0 = (Q chunk 0, SK chunk 0 of tile 0)
    f_load_rk(smQC[0], Qb, qbase, 0, tid);
    f_load_rk(smSKC[0], SKb, 0, 0, tid);
    CP_COMMIT();

    float Oacc[4][8][4];
#pragma unroll
    for (int i = 0; i < 4; i++)
#pragma unroll
        for (int j = 0; j < 8; j++)
#pragma unroll
            for (int v = 0; v < 4; v++) Oacc[i][j][v] = 0.f;
    float rsum[4][2];
#pragma unroll
    for (int i = 0; i < 4; i++) { rsum[i][0] = 0.f; rsum[i][1] = 0.f; }

    constexpr float EXPC = 0.09016844f;              // log2(e)/16

    for (int t = 0; t < 32; t++) {
        const int s0 = t * FST;
        float Sacc[4][4][4];
#pragma unroll
        for (int i = 0; i < 4; i++)
#pragma unroll
            for (int j = 0; j < 4; j++)
#pragma unroll
                for (int v = 0; v < 4; v++) Sacc[i][j][v] = 0.f;

        // ---- S = Q @ SK_tile^T over k=256 in 8 chunks ----
        for (int c = 0; c < 8; c++) {
            CP_WAIT(0);
            __syncthreads();
            if (c < 7) {
                f_load_rk(smQC[(c + 1) & 1], Qb, qbase, c + 1, tid);
                f_load_rk(smSKC[(c + 1) & 1], SKb, s0, c + 1, tid);
                CP_COMMIT();
            } else {
                f_load_v(smV[0], Vtb, s0, 0, tid);
                CP_COMMIT();
            }
            const float* Qs  = (const float*)(smem + OFF_QC  + (c & 1) * CHUNK_B);
            const float* Sks = (const float*)(smem + OFF_SKC + (c & 1) * CHUNK_B);
#pragma unroll
            for (int step = 0; step < 4; step++) {
                const int k0 = step * 8;
                uint32_t afr[4][4];
#pragma unroll
                for (int i = 0; i < 4; i++) {
                    int r = wm * 64 + i * 16 + g;
                    afr[i][0] = __float_as_uint(Qs[r * FSTR + k0 + tg]);
                    afr[i][1] = __float_as_uint(Qs[(r + 8) * FSTR + k0 + tg]);
                    afr[i][2] = __float_as_uint(Qs[r * FSTR + k0 + tg + 4]);
                    afr[i][3] = __float_as_uint(Qs[(r + 8) * FSTR + k0 + tg + 4]);
                }
#pragma unroll
                for (int j = 0; j < 4; j++) {
                    int n = wn * 32 + j * 8 + g;
                    uint32_t b0 = __float_as_uint(Sks[n * FSTR + k0 + tg]);
                    uint32_t b1 = __float_as_uint(Sks[n * FSTR + k0 + tg + 4]);
#pragma unroll
                    for (int i = 0; i < 4; i++)
                        mma8(Sacc[i][j], afr[i][0], afr[i][1], afr[i][2], afr[i][3], b0, b1);
                }
            }
        }

        // ---- P = exp(S/16); accumulate rowsums; stage P in smem ----
#pragma unroll
        for (int i = 0; i < 4; i++) {
            int r = wm * 64 + i * 16 + g;
#pragma unroll
            for (int j = 0; j < 4; j++) {
                int col = wn * 32 + j * 8 + t2;
                float p0 = exp2f(Sacc[i][j][0] * EXPC);
                float p1 = exp2f(Sacc[i][j][1] * EXPC);
                float p2 = exp2f(Sacc[i][j][2] * EXPC);
                float p3 = exp2f(Sacc[i][j][3] * EXPC);
                rsum[i][0] += p0 + p1;
                rsum[i][1] += p2 + p3;
                *(float2*)&Ps[r * PSTR + col]       = make_float2(p0, p1);
                *(float2*)&Ps[(r + 8) * PSTR + col] = make_float2(p2, p3);
            }
        }

        // ---- O += P @ V_tile over s=128 in 4 chunks ----
        for (int v = 0; v < 4; v++) {
            CP_WAIT(0);
            __syncthreads();                          // V chunk ready; P visible (v==0)
            if (v < 3) {
                f_load_v(smV[(v + 1) & 1], Vtb, s0, v + 1, tid);
                CP_COMMIT();
            } else if (t < 31) {
                f_load_rk(smQC[0], Qb, qbase, 0, tid);
                f_load_rk(smSKC[0], SKb, s0 + FST, 0, tid);
                CP_COMMIT();
            }
            const float* Vs = (const float*)(smem + OFF_V + (v & 1) * VCHUNK_B);
#pragma unroll
            for (int step = 0; step < 4; step++) {
                const int pk = v * 32 + step * 8;
                const int k0 = step * 8;
                uint32_t afr[4][4];
#pragma unroll
                for (int i = 0; i < 4; i++) {
                    int r = wm * 64 + i * 16 + g;
                    afr[i][0] = __float_as_uint(Ps[r * PSTR + pk + tg]);
                    afr[i][1] = __float_as_uint(Ps[(r + 8) * PSTR + pk + tg]);
                    afr[i][2] = __float_as_uint(Ps[r * PSTR + pk + tg + 4]);
                    afr[i][3] = __float_as_uint(Ps[(r + 8) * PSTR + pk + tg + 4]);
                }
#pragma unroll
                for (int j = 0; j < 8; j++) {
                    int n = wn * 64 + j * 8 + g;
                    uint32_t b0 = __float_as_uint(Vs[n * FSTR + k0 + tg]);
                    uint32_t b1 = __float_as_uint(Vs[n * FSTR + k0 + tg + 4]);
#pragma unroll
                    for (int i = 0; i < 4; i++)
                        mma8(Oacc[i][j], afr[i][0], afr[i][1], afr[i][2], afr[i][3], b0, b1);
                }
            }
        }
    }

    // ---- rowsum reduce: across tg lanes then across wn warps ----
#pragma unroll
    for (int i = 0; i < 4; i++)
#pragma unroll
        for (int h = 0; h < 2; h++) {
            float v = rsum[i][h];
            v += __shfl_xor_sync(0xffffffffu, v, 1);
            v += __shfl_xor_sync(0xffffffffu, v, 2);
            rsum[i][h] = v;
        }
    if (tg == 0) {
#pragma unroll
        for (int i = 0; i < 4; i++) {
            atomicAdd(&rowsumS[wm * 64 + i * 16 + g], rsum[i][0]);
            atomicAdd(&rowsumS[wm * 64 + i * 16 + g + 8], rsum[i][1]);
        }
    }
    __syncthreads();

    // ---- normalize + write O ----
#pragma unroll
    for (int i = 0; i < 4; i++) {
        int r = wm * 64 + i * 16 + g;
        float inv0 = 1.f / rowsumS[r];
        float inv1 = 1.f / rowsumS[r + 8];
        float* orow0 = Ob + (size_t)(qbase + r) * DIM;
        float* orow1 = orow0 + (size_t)8 * DIM;
#pragma unroll
        for (int j = 0; j < 8; j++) {
            int c = wn * 64 + j * 8 + t2;
            *(float2*)(orow0 + c) = make_float2(Oacc[i][j][0] * inv0, Oacc[i][j][1] * inv0);
            *(float2*)(orow1 + c) = make_float2(Oacc[i][j][2] * inv1, Oacc[i][j][3] * inv1);
        }
    }
}

// ---------------- V transpose: Vt[b,d,s] = V[b,s,d] ----------------
__global__ void transpose_v(const float* __restrict__ V, float* __restrict__ Vt) {
    __shared__ float t[32][33];
    int b = blockIdx.z;
    int s0 = blockIdx.x * 32, d0 = blockIdx.y * 32;
    const float* Vb = V + (size_t)b * SEQ * DIM;
    float* Vtb = Vt + (size_t)b * SEQ * DIM;
    int x = threadIdx.x, y = threadIdx.y;
#pragma unroll
    for (int i = 0; i < 32; i += 8)
        t[y + i][x] = Vb[(size_t)(s0 + y + i) * DIM + d0 + x];
    __syncthreads();
#pragma unroll
    for (int i = 0; i < 32; i += 8)
        Vtb[(size_t)(d0 + y + i) * SEQ + s0 + x] = t[x][y + i];
}

// ---------------- prefix sums of K rows (analytic sparse@K) ----------------
__global__ void prefix_partial(const float* __restrict__ Kmat, float* __restrict__ pp) {
    int ch = blockIdx.x, b = blockIdx.y, d = threadIdx.x;
    int s0 = ch * 128;
    int s1 = min(s0 + 128, 2047);
    const float* Kb = Kmat + (size_t)b * SEQ * DIM;
    float s = 0.f;
    for (int ss = s0; ss < s1; ss++) s += Kb[(size_t)ss * DIM + d];
    pp[((size_t)b * 16 + ch) * DIM + d] = s;
}

__global__ void prefix_combine(const float* __restrict__ Kmat,
                               const float* __restrict__ pp, float* __restrict__ P) {
    int b = blockIdx.x, d = threadIdx.x;
    const float* Kb = Kmat + (size_t)b * SEQ * DIM;
    float s = 0.f;
    for (int ch = 0; ch < 16; ch++) s += pp[((size_t)b * 16 + ch) * DIM + d];
    float p2047 = s;
    float p2048 = p2047 + Kb[(size_t)2047 * DIM + d];
    float p2049 = p2048 + Kb[(size_t)2048 * DIM + d];
    float p2052 = p2049 + Kb[(size_t)2049 * DIM + d]
                        + Kb[(size_t)2050 * DIM + d]
                        + Kb[(size_t)2051 * DIM + d];
    float* Pb = P + (size_t)b * 4 * DIM;
    Pb[0 * DIM + d] = p2047;
    Pb[1 * DIM + d] = p2048;
    Pb[2 * DIM + d] = p2049;
    Pb[3 * DIM + d] = p2052;
}

__global__ void sk_kernel(const float* __restrict__ Kmat, const float* __restrict__ P,
                          float* __restrict__ SK,
                          float A3, float B3, float A4, float B4, float A5, float B5) {
    int i = blockIdx.x, b = blockIdx.y, d = threadIdx.x;
    const float* Kb = Kmat + (size_t)b * SEQ * DIM;
    int lo = max(i - 2, 0), hi = min(i + 2, SEQ - 1);
    int n = hi - lo + 1;
    float band = 0.f;
    for (int j = lo; j <= hi; j++) band += Kb[(size_t)j * DIM + d];
    const float* Pb = P + (size_t)b * 4 * DIM;
    float off;
    if (i <= 2048) off = Pb[3 * DIM + d] - band;
    else           off = Pb[(5 - n) * DIM + d];
    float a, bb;
    if (n == 5)      { a = A5; bb = B5; }
    else if (n == 4) { a = A4; bb = B4; }
    else             { a = A3; bb = B3; }
    SK[((size_t)b * SEQ + i) * DIM + d] = a * band + bb * off;
}

// ---------------- full-tensor LayerNorm ----------------
__global__ void ln_partial(const float* __restrict__ x1, const float* __restrict__ x2,
                           float* __restrict__ part) {
    int tid = threadIdx.x, bid = blockIdx.x;
    float s = 0.f, ss = 0.f;
    for (size_t i = (size_t)bid * 256 + tid; i < TXT_N; i += (size_t)2048 * 256) {
        float v = x1[i] + x2[i];
        s += v;
        ss = fmaf(v, v, ss);
    }
    __shared__ float rs[256], rss[256];
    rs[tid] = s; rss[tid] = ss;
    __syncthreads();
    for (int o = 128; o; o >>= 1) {
        if (tid < o) { rs[tid] += rs[tid + o]; rss[tid] += rss[tid + o]; }
        __syncthreads();
    }
    if (tid == 0) { part[bid] = rs[0]; part[2048 + bid] = rss[0]; }
}

__global__ void ln_combine(const float* __restrict__ part, float* __restrict__ stats) {
    __shared__ double sd[256], ssd[256];
    int tid = threadIdx.x;
    double s = 0.0, ss = 0.0;
    for (int i = tid; i < 2048; i += 256) { s += part[i]; ss += part[2048 + i]; }
    sd[tid] = s; ssd[tid] = ss;
    __syncthreads();
    for (int o = 128; o; o >>= 1) {
        if (tid < o) { sd[tid] += sd[tid + o]; ssd[tid] += ssd[tid + o]; }
        __syncthreads();
    }
    if (tid == 0) {
        double n = (double)TXT_N;
        double mu = sd[0] / n;
        double var = ssd[0] / n - mu * mu;
        stats[0] = (float)mu;
        stats[1] = (float)(1.0 / sqrt(var + 1e-6));
    }
}

__global__ void ln_apply(const float* __restrict__ x1, const float* __restrict__ x2,
                         const float* __restrict__ g, const float* __restrict__ bta,
                         const float* __restrict__ stats, float* __restrict__ out) {
    size_t i = (size_t)blockIdx.x * 256 + threadIdx.x;
    float mu = stats[0], r = stats[1];
    float v = x1[i] + x2[i];
    out[i] = (v - mu) * r * g[i] + bta[i];
}

__global__ void copy_img(const float* __restrict__ src, float* __restrict__ dst, int n) {
    int i = blockIdx.x * 256 + threadIdx.x;
    if (i < n) dst[i] = src[i];
}

// ---------------- launch ----------------
extern "C" void kernel_launch(void* const* d_in, const int* in_sizes, int n_in,
                              void* d_out, int out_size) {
    const float* text  = (const float*)d_in[0];
    const float* image = (const float*)d_in[1];
    const float* Wq = (const float*)d_in[2];
    const float* bq = (const float*)d_in[3];
    const float* Wk = (const float*)d_in[4];
    const float* bk = (const float*)d_in[5];
    const float* Wv = (const float*)d_in[6];
    const float* bv = (const float*)d_in[7];
    const float* W1 = (const float*)d_in[8];
    const float* b1 = (const float*)d_in[9];
    const float* W2 = (const float*)d_in[10];
    const float* b2 = (const float*)d_in[11];
    const float* gamma = (const float*)d_in[12];
    const float* beta  = (const float*)d_in[13];
    float* out = (float*)d_out;

    float *Q, *K, *V, *Vt, *SK, *O, *H, *M2, *FF, *part, *stats, *P, *pp;
    cudaGetSymbolAddress((void**)&Q,  g_Q);
    cudaGetSymbolAddress((void**)&K,  g_K);
    cudaGetSymbolAddress((void**)&V,  g_V);
    cudaGetSymbolAddress((void**)&Vt, g_Vt);
    cudaGetSymbolAddress((void**)&SK, g_SK);
    cudaGetSymbolAddress((void**)&O,  g_O);
    cudaGetSymbolAddress((void**)&H,  g_H);
    cudaGetSymbolAddress((void**)&M2, g_M2);
    cudaGetSymbolAddress((void**)&FF, g_FF);
    cudaGetSymbolAddress((void**)&part, g_part);
    cudaGetSymbolAddress((void**)&stats, g_stats);
    cudaGetSymbolAddress((void**)&P,  g_P);
    cudaGetSymbolAddress((void**)&pp, g_pp);

    static int smem_set = 0;
    if (!smem_set) {
        cudaFuncSetAttribute(tc_gemm, cudaFuncAttributeMaxDynamicSharedMemorySize, GEMM_SMEM);
        cudaFuncSetAttribute(flash_attn, cudaFuncAttributeMaxDynamicSharedMemorySize, FLASH_SMEM);
        smem_set = 1;
    }

    // sparse-softmax coefficients
    double e = exp(1.0);
    float A[6], Bc[6];
    for (int n = 3; n <= 5; n++) {
        double Z = n * e + (double)(SEQ - n);
        A[n]  = (float)(e / Z);
        Bc[n] = (float)(1.0 / Z);
    }

    // QKV projections
    tc_gemm<<<dim3(2, 128, 1), 256, GEMM_SMEM>>>(text, Wq, Q, NTOK, DIM, DIM, 0, 0, 0, 1.f, bq, 0);
    tc_gemm<<<dim3(2, 128, 1), 256, GEMM_SMEM>>>(text, Wk, K, NTOK, DIM, DIM, 0, 0, 0, 1.f, bk, 0);
    tc_gemm<<<dim3(2, 128, 1), 256, GEMM_SMEM>>>(text, Wv, V, NTOK, DIM, DIM, 0, 0, 0, 1.f, bv, 0);

    transpose_v<<<dim3(128, 8, BATCH), dim3(32, 8)>>>(V, Vt);

    // analytic sparse @ K
    prefix_partial<<<dim3(16, BATCH), 256>>>(K, pp);
    prefix_combine<<<BATCH, 256>>>(K, pp, P);
    sk_kernel<<<dim3(SEQ, BATCH), 256>>>(K, P, SK, A[3], Bc[3], A[4], Bc[4], A[5], Bc[5]);

    // fused attention: O = softmax(Q@SK^T/16) @ V
    flash_attn<<<dim3(SEQ / FQT, BATCH), 256, FLASH_SMEM>>>(Q, SK, Vt, O);

    // LN1 over full tensor of (O + text) -> H
    ln_partial<<<2048, 256>>>(O, text, part);
    ln_combine<<<1, 256>>>(part, stats);
    ln_apply<<<NTOK, 256>>>(O, text, gamma, beta, stats, H);

    // MLP
    tc_gemm<<<dim3(8, 128, 1), 256, GEMM_SMEM>>>(H, W1, FF, NTOK, DFF, DIM, 0, 0, 0, 1.f, b1, 1);
    tc_gemm<<<dim3(2, 128, 1), 256, GEMM_SMEM>>>(FF, W2, M2, NTOK, DIM, DFF, 0, 0, 0, 1.f, b2, 0);

    // LN2 over full tensor of (M2 + text) -> out
    ln_partial<<<2048, 256>>>(M2, text, part);
    ln_combine<<<1, 256>>>(part, stats);
    ln_apply<<<NTOK, 256>>>(M2, text, gamma, beta, stats, out);

    // image passthrough
    if (out_size >= (int)TXT_N + IMG_N) {
        copy_img<<<(IMG_N + 255) / 256, 256>>>(image, out + TXT_N, IMG_N);
    }
}

// round 7
// speedup vs baseline: 4.7550x; 1.4233x over previous
#include <cuda_runtime.h>
#include <cuda_bf16.h>
#include <math.h>
#include <stdint.h>

// ---------------- problem constants ----------------
constexpr int BATCH = 4;
constexpr int SEQ   = 4096;
constexpr int DIM   = 256;
constexpr int DFF   = 1024;
constexpr int NTOK  = BATCH * SEQ;                 // 16384
constexpr size_t TXT_N = (size_t)NTOK * DIM;       // 4,194,304
constexpr int IMG_N = BATCH * 196 * DIM;           // 200,704

// ---------------- scratch (device globals; no allocs allowed) ----------------
__device__ __nv_bfloat16 g_Qbf [4194304];
__device__ __nv_bfloat16 g_SKbf[4194304];
__device__ __nv_bfloat16 g_Vtbf[4194304];
__device__ float g_K [4194304];
__device__ float g_V [4194304];
__device__ float g_O [4194304];
__device__ float g_H [4194304];
__device__ float g_M2[4194304];
__device__ float g_FF[16777216];                   // [16384, 1024]
__device__ float g_part[4096];
__device__ float g_stats[2];
__device__ float g_P [BATCH * 4 * DIM];
__device__ float g_pp[BATCH * 16 * DIM];

// ================= async copy helpers (baseline PTX, sm_80+) =================
__device__ __forceinline__ uint32_t smem_u32(const void* p) {
    uint32_t a;
    asm("{ .reg .u64 t; cvta.to.shared.u64 t, %1; cvt.u32.u64 %0, t; }" : "=r"(a) : "l"(p));
    return a;
}
#define CP16(dst, src) \
    asm volatile("cp.async.cg.shared.global [%0], [%1], 16;" :: "r"(dst), "l"(src))
#define CP_COMMIT() asm volatile("cp.async.commit_group;" ::: "memory")
#define CP_WAIT(n)  asm volatile("cp.async.wait_group %0;" :: "n"(n) : "memory")

// mma.sync m16n8k8 tf32 (row.col): D += A*B
__device__ __forceinline__ void mma8(float* c, uint32_t a0, uint32_t a1,
                                     uint32_t a2, uint32_t a3, uint32_t b0, uint32_t b1) {
    asm volatile(
        "mma.sync.aligned.m16n8k8.row.col.f32.tf32.tf32.f32 "
        "{%0,%1,%2,%3}, {%4,%5,%6,%7}, {%8,%9}, {%0,%1,%2,%3};\n"
        : "+f"(c[0]), "+f"(c[1]), "+f"(c[2]), "+f"(c[3])
        : "r"(a0), "r"(a1), "r"(a2), "r"(a3), "r"(b0), "r"(b1));
}
// mma.sync m16n8k16 bf16 (row.col): D += A*B
__device__ __forceinline__ void mma16(float* c, uint32_t a0, uint32_t a1,
                                      uint32_t a2, uint32_t a3, uint32_t b0, uint32_t b1) {
    asm volatile(
        "mma.sync.aligned.m16n8k16.row.col.f32.bf16.bf16.f32 "
        "{%0,%1,%2,%3}, {%4,%5,%6,%7}, {%8,%9}, {%0,%1,%2,%3};\n"
        : "+f"(c[0]), "+f"(c[1]), "+f"(c[2]), "+f"(c[3])
        : "r"(a0), "r"(a1), "r"(a2), "r"(a3), "r"(b0), "r"(b1));
}
__device__ __forceinline__ uint32_t pack_bf2(float x, float y) {
    __nv_bfloat162 h = __float22bfloat162_rn(make_float2(x, y));
    return *(uint32_t*)&h;
}

// ================= tf32 tensor-core GEMM: C = alpha*A@B^T (+bias)(+relu) ======
constexpr int TCBM = 128, TCBN = 128, TCBK = 32;
constexpr int ASTRIDE = 36;
constexpr int STAGE_BYTES = 128 * ASTRIDE * 4;      // 18432
constexpr int GEMM_SMEM = 4 * STAGE_BYTES;          // 73728

__device__ __forceinline__ void load_stage_tc(
    uint32_t smA, uint32_t smB,
    const float* __restrict__ Ab, const float* __restrict__ Bb,
    int K, int k0, int tid)
{
#pragma unroll
    for (int it = 0; it < 4; it++) {
        int idx = tid + it * 256;
        int row = idx >> 3, seg = idx & 7;
        CP16(smA + (uint32_t)(row * ASTRIDE + seg * 4) * 4,
             Ab + (size_t)row * K + k0 + seg * 4);
    }
#pragma unroll
    for (int it = 0; it < 4; it++) {
        int idx = tid + it * 256;
        int row = idx >> 3, seg = idx & 7;
        CP16(smB + (uint32_t)(row * ASTRIDE + seg * 4) * 4,
             Bb + (size_t)row * K + k0 + seg * 4);
    }
}

__global__ void __launch_bounds__(256) tc_gemm(
    const float* __restrict__ A, const float* __restrict__ B, float* __restrict__ C,
    int M, int N, int K, long long sA, long long sB, long long sC,
    float alpha, const float* __restrict__ bias, int relu, int out_bf16)
{
    extern __shared__ char smem[];
    const int tid = threadIdx.x;
    const int wid = tid >> 5, lane = tid & 31;
    const int wm = wid & 3, wn = wid >> 2;
    const int g = lane >> 2;
    const int tg = lane & 3;
    const int t2 = tg << 1;
    const int bx = blockIdx.x, by = blockIdx.y, bz = blockIdx.z;
    const int m0 = by * TCBM, n0 = bx * TCBN;
    const float* Ab = A + (size_t)bz * sA + (size_t)m0 * K;
    const float* Bb = B + (size_t)bz * sB + (size_t)n0 * K;
    float*       Cb = C + (size_t)bz * sC;

    const uint32_t sbase = smem_u32(smem);
    const uint32_t smA[2] = { sbase, sbase + STAGE_BYTES };
    const uint32_t smB[2] = { sbase + 2 * STAGE_BYTES, sbase + 3 * STAGE_BYTES };

    float acc[2][8][4];
#pragma unroll
    for (int i = 0; i < 2; i++)
#pragma unroll
        for (int j = 0; j < 8; j++)
#pragma unroll
            for (int v = 0; v < 4; v++) acc[i][j][v] = 0.f;

    const int KT = K / TCBK;
    load_stage_tc(smA[0], smB[0], Ab, Bb, K, 0, tid);
    CP_COMMIT();

    for (int kt = 0; kt < KT; kt++) {
        const int cur = kt & 1;
        if (kt + 1 < KT) {
            load_stage_tc(smA[cur ^ 1], smB[cur ^ 1], Ab, Bb, K, (kt + 1) * TCBK, tid);
            CP_COMMIT();
            CP_WAIT(1);
        } else {
            CP_WAIT(0);
        }
        __syncthreads();

        const float* As = (const float*)(smem + (size_t)cur * STAGE_BYTES);
        const float* Bs = (const float*)(smem + (size_t)(2 + cur) * STAGE_BYTES);
#pragma unroll
        for (int step = 0; step < 4; step++) {
            const int k0 = step * 8;
            uint32_t afr[2][4];
#pragma unroll
            for (int i = 0; i < 2; i++) {
                int r = wm * 32 + i * 16 + g;
                afr[i][0] = __float_as_uint(As[r * ASTRIDE + k0 + tg]);
                afr[i][1] = __float_as_uint(As[(r + 8) * ASTRIDE + k0 + tg]);
                afr[i][2] = __float_as_uint(As[r * ASTRIDE + k0 + tg + 4]);
                afr[i][3] = __float_as_uint(As[(r + 8) * ASTRIDE + k0 + tg + 4]);
            }
#pragma unroll
            for (int j = 0; j < 8; j++) {
                int n = wn * 64 + j * 8 + g;
                uint32_t b0 = __float_as_uint(Bs[n * ASTRIDE + k0 + tg]);
                uint32_t b1 = __float_as_uint(Bs[n * ASTRIDE + k0 + tg + 4]);
#pragma unroll
                for (int i = 0; i < 2; i++) {
                    mma8(acc[i][j], afr[i][0], afr[i][1], afr[i][2], afr[i][3], b0, b1);
                }
            }
        }
        __syncthreads();
    }

#pragma unroll
    for (int i = 0; i < 2; i++) {
        int r = m0 + wm * 32 + i * 16 + g;
#pragma unroll
        for (int j = 0; j < 8; j++) {
            int c = n0 + wn * 64 + j * 8 + t2;
            float2 v0, v1;
            v0.x = acc[i][j][0] * alpha; v0.y = acc[i][j][1] * alpha;
            v1.x = acc[i][j][2] * alpha; v1.y = acc[i][j][3] * alpha;
            if (bias) {
                float bb0 = __ldg(bias + c), bb1 = __ldg(bias + c + 1);
                v0.x += bb0; v0.y += bb1;
                v1.x += bb0; v1.y += bb1;
            }
            if (relu) {
                v0.x = fmaxf(v0.x, 0.f); v0.y = fmaxf(v0.y, 0.f);
                v1.x = fmaxf(v1.x, 0.f); v1.y = fmaxf(v1.y, 0.f);
            }
            if (out_bf16) {
                uint32_t* cb = (uint32_t*)Cb;
                cb[((size_t)r * N + c) >> 1]              = pack_bf2(v0.x, v0.y);
                cb[((size_t)(r + 8) * N + c) >> 1]        = pack_bf2(v1.x, v1.y);
            } else {
                *(float2*)(Cb + (size_t)r * N + c)       = v0;
                *(float2*)(Cb + (size_t)(r + 8) * N + c) = v1;
            }
        }
    }
}

// ================= bf16 fused flash attention: FQT=128, Q resident ===========
// O = exp(Q@SK^T/16) @ V / rowsum. 512 threads = 16 warps (4m x 4n).
// Q resident (128x256 bf16); SK streamed in 64-k chunks (db); P bf16 in smem;
// Vt streamed in 64-s chunks (db).
constexpr int FQT = 128;
constexpr int FST = 128;
constexpr int QW = 132;                              // words per Q row
constexpr int SKW = 36;                              // words per SK/V chunk row
constexpr int PW = 68;                               // words per P row
constexpr int SK_CHUNK_B = 128 * SKW * 4;            // 18432
constexpr int V_CHUNK_B  = 256 * SKW * 4;            // 36864
constexpr int OFF_Q  = 0;                            // 128*132*4 = 67584
constexpr int OFF_SK = 67584;                        // 2*18432 = 36864
constexpr int OFF_P  = 104448;                       // 128*68*4 = 34816
constexpr int OFF_V  = 139264;                       // 2*36864 = 73728
constexpr int OFF_RS = 212992;                       // 512
constexpr int FLASH_SMEM = 213504;

__device__ __forceinline__ void f_load_q(uint32_t dst, const __nv_bfloat16* __restrict__ Qb,
                                         int qbase, int tid) {
#pragma unroll
    for (int it = 0; it < 8; it++) {
        int idx = tid + it * 512;                    // 0..4095
        int row = idx >> 5, seg = idx & 31;
        CP16(dst + (uint32_t)(row * QW + seg * 4) * 4,
             Qb + (size_t)(qbase + row) * DIM + seg * 8);
    }
}
__device__ __forceinline__ void f_load_sk(uint32_t dst, const __nv_bfloat16* __restrict__ SKb,
                                          int s0, int kc, int tid) {
#pragma unroll
    for (int it = 0; it < 2; it++) {
        int idx = tid + it * 512;                    // 0..1023
        int row = idx >> 3, seg = idx & 7;
        CP16(dst + (uint32_t)(row * SKW + seg * 4) * 4,
             SKb + (size_t)(s0 + row) * DIM + kc * 64 + seg * 8);
    }
}
__device__ __forceinline__ void f_load_v(uint32_t dst, const __nv_bfloat16* __restrict__ Vtb,
                                         int s0, int vc, int tid) {
#pragma unroll
    for (int it = 0; it < 4; it++) {
        int idx = tid + it * 512;                    // 0..2047
        int row = idx >> 3, seg = idx & 7;
        CP16(dst + (uint32_t)(row * SKW + seg * 4) * 4,
             Vtb + (size_t)row * SEQ + s0 + vc * 64 + seg * 8);
    }
}

__global__ void __launch_bounds__(512, 1) flash_attn(
    const __nv_bfloat16* __restrict__ Q, const __nv_bfloat16* __restrict__ SK,
    const __nv_bfloat16* __restrict__ Vt, float* __restrict__ O)
{
    extern __shared__ char smem[];
    const int tid = threadIdx.x;
    const int wid = tid >> 5, lane = tid & 31;
    const int wm = wid & 3, wn = wid >> 2;           // 4m x 4n
    const int g = lane >> 2, tg = lane & 3, t2 = tg << 1;
    const int qbase = blockIdx.x * FQT;
    const int b = blockIdx.y;

    const __nv_bfloat16* Qb  = Q  + (size_t)b * SEQ * DIM;
    const __nv_bfloat16* SKb = SK + (size_t)b * SEQ * DIM;
    const __nv_bfloat16* Vtb = Vt + (size_t)b * SEQ * DIM;
    float*               Ob  = O  + (size_t)b * SEQ * DIM;

    const uint32_t sbase = smem_u32(smem);
    const uint32_t smSKC[2] = { sbase + OFF_SK, sbase + OFF_SK + SK_CHUNK_B };
    const uint32_t smV[2]   = { sbase + OFF_V,  sbase + OFF_V  + V_CHUNK_B };
    const uint32_t* Qs32 = (const uint32_t*)(smem + OFF_Q);
    uint32_t* Ps32 = (uint32_t*)(smem + OFF_P);
    float* rowsumS = (float*)(smem + OFF_RS);

    if (tid < FQT) rowsumS[tid] = 0.f;

    f_load_q(sbase + OFF_Q, Qb, qbase, tid);
    f_load_sk(smSKC[0], SKb, 0, 0, tid);
    CP_COMMIT();

    float Oacc[2][8][4];
#pragma unroll
    for (int i = 0; i < 2; i++)
#pragma unroll
        for (int j = 0; j < 8; j++)
#pragma unroll
            for (int v = 0; v < 4; v++) Oacc[i][j][v] = 0.f;
    float rsum[2][2] = {{0.f, 0.f}, {0.f, 0.f}};

    constexpr float EXPC = 0.09016844f;              // log2(e)/16

    for (int t = 0; t < 32; t++) {
        const int s0 = t * FST;
        float Sacc[2][4][4];
#pragma unroll
        for (int i = 0; i < 2; i++)
#pragma unroll
            for (int j = 0; j < 4; j++)
#pragma unroll
                for (int v = 0; v < 4; v++) Sacc[i][j][v] = 0.f;

        // ---- S = Q @ SK_tile^T over k=256 in 4 chunks of 64 ----
        for (int c = 0; c < 4; c++) {
            CP_WAIT(0);
            __syncthreads();
            if (c < 3) { f_load_sk(smSKC[(c + 1) & 1], SKb, s0, c + 1, tid); CP_COMMIT(); }
            else       { f_load_v(smV[0], Vtb, s0, 0, tid); CP_COMMIT(); }
            const uint32_t* Sks = (const uint32_t*)(smem + OFF_SK + (c & 1) * SK_CHUNK_B);
#pragma unroll
            for (int step = 0; step < 4; step++) {
                const int qw = c * 32 + step * 8;    // Q word offset
                const int kw = step * 8;             // chunk word offset
                uint32_t afr[2][4];
#pragma unroll
                for (int i = 0; i < 2; i++) {
                    int r = wm * 32 + i * 16 + g;
                    afr[i][0] = Qs32[r * QW + qw + tg];
                    afr[i][1] = Qs32[(r + 8) * QW + qw + tg];
                    afr[i][2] = Qs32[r * QW + qw + tg + 4];
                    afr[i][3] = Qs32[(r + 8) * QW + qw + tg + 4];
                }
#pragma unroll
                for (int j = 0; j < 4; j++) {
                    int n = wn * 32 + j * 8 + g;
                    uint32_t b0 = Sks[n * SKW + kw + tg];
                    uint32_t b1 = Sks[n * SKW + kw + tg + 4];
#pragma unroll
                    for (int i = 0; i < 2; i++)
                        mma16(Sacc[i][j], afr[i][0], afr[i][1], afr[i][2], afr[i][3], b0, b1);
                }
            }
        }

        // ---- P = exp(S/16) packed bf16x2; accumulate rowsums ----
#pragma unroll
        for (int i = 0; i < 2; i++) {
            int r = wm * 32 + i * 16 + g;
#pragma unroll
            for (int j = 0; j < 4; j++) {
                int cw = wn * 16 + j * 4 + tg;       // P word column
                float p0 = exp2f(Sacc[i][j][0] * EXPC);
                float p1 = exp2f(Sacc[i][j][1] * EXPC);
                float p2 = exp2f(Sacc[i][j][2] * EXPC);
                float p3 = exp2f(Sacc[i][j][3] * EXPC);
                rsum[i][0] += p0 + p1;
                rsum[i][1] += p2 + p3;
                Ps32[r * PW + cw]       = pack_bf2(p0, p1);
                Ps32[(r + 8) * PW + cw] = pack_bf2(p2, p3);
            }
        }

        // ---- O += P @ V_tile over s=128 in 2 chunks of 64 ----
        for (int v = 0; v < 2; v++) {
            CP_WAIT(0);
            __syncthreads();                          // V chunk ready; P visible (v==0)
            if (v == 0)      { f_load_v(smV[1], Vtb, s0, 1, tid); CP_COMMIT(); }
            else if (t < 31) { f_load_sk(smSKC[0], SKb, s0 + FST, 0, tid); CP_COMMIT(); }
            const uint32_t* Vs = (const uint32_t*)(smem + OFF_V + v * V_CHUNK_B);
#pragma unroll
            for (int step = 0; step < 4; step++) {
                const int pw = v * 32 + step * 8;    // P word offset (s within tile)
                const int kw = step * 8;
                uint32_t afr[2][4];
#pragma unroll
                for (int i = 0; i < 2; i++) {
                    int r = wm * 32 + i * 16 + g;
                    afr[i][0] = Ps32[r * PW + pw + tg];
                    afr[i][1] = Ps32[(r + 8) * PW + pw + tg];
                    afr[i][2] = Ps32[r * PW + pw + tg + 4];
                    afr[i][3] = Ps32[(r + 8) * PW + pw + tg + 4];
                }
#pragma unroll
                for (int j = 0; j < 8; j++) {
                    int n = wn * 64 + j * 8 + g;
                    uint32_t b0 = Vs[n * SKW + kw + tg];
                    uint32_t b1 = Vs[n * SKW + kw + tg + 4];
#pragma unroll
                    for (int i = 0; i < 2; i++)
                        mma16(Oacc[i][j], afr[i][0], afr[i][1], afr[i][2], afr[i][3], b0, b1);
                }
            }
        }
    }

    // ---- rowsum reduce ----
#pragma unroll
    for (int i = 0; i < 2; i++)
#pragma unroll
        for (int h = 0; h < 2; h++) {
            float v = rsum[i][h];
            v += __shfl_xor_sync(0xffffffffu, v, 1);
            v += __shfl_xor_sync(0xffffffffu, v, 2);
            rsum[i][h] = v;
        }
    if (tg == 0) {
#pragma unroll
        for (int i = 0; i < 2; i++) {
            atomicAdd(&rowsumS[wm * 32 + i * 16 + g], rsum[i][0]);
            atomicAdd(&rowsumS[wm * 32 + i * 16 + g + 8], rsum[i][1]);
        }
    }
    __syncthreads();

    // ---- normalize + write O ----
#pragma unroll
    for (int i = 0; i < 2; i++) {
        int r = wm * 32 + i * 16 + g;
        float inv0 = 1.f / rowsumS[r];
        float inv1 = 1.f / rowsumS[r + 8];
        float* orow0 = Ob + (size_t)(qbase + r) * DIM;
        float* orow1 = orow0 + (size_t)8 * DIM;
#pragma unroll
        for (int j = 0; j < 8; j++) {
            int c = wn * 64 + j * 8 + t2;
            *(float2*)(orow0 + c) = make_float2(Oacc[i][j][0] * inv0, Oacc[i][j][1] * inv0);
            *(float2*)(orow1 + c) = make_float2(Oacc[i][j][2] * inv1, Oacc[i][j][3] * inv1);
        }
    }
}

// ---------------- V transpose -> bf16: Vt[b,d,s] = bf16(V[b,s,d]) -------------
__global__ void transpose_v(const float* __restrict__ V, __nv_bfloat16* __restrict__ Vt) {
    __shared__ float t[32][33];
    int b = blockIdx.z;
    int s0 = blockIdx.x * 32, d0 = blockIdx.y * 32;
    const float* Vb = V + (size_t)b * SEQ * DIM;
    __nv_bfloat16* Vtb = Vt + (size_t)b * SEQ * DIM;
    int x = threadIdx.x, y = threadIdx.y;
#pragma unroll
    for (int i = 0; i < 32; i += 8)
        t[y + i][x] = Vb[(size_t)(s0 + y + i) * DIM + d0 + x];
    __syncthreads();
#pragma unroll
    for (int i = 0; i < 32; i += 8)
        Vtb[(size_t)(d0 + y + i) * SEQ + s0 + x] = __float2bfloat16(t[x][y + i]);
}

// ---------------- prefix sums of K rows (analytic sparse@K) ----------------
__global__ void prefix_partial(const float* __restrict__ Kmat, float* __restrict__ pp) {
    int ch = blockIdx.x, b = blockIdx.y, d = threadIdx.x;
    int s0 = ch * 128;
    int s1 = min(s0 + 128, 2047);
    const float* Kb = Kmat + (size_t)b * SEQ * DIM;
    float s = 0.f;
    for (int ss = s0; ss < s1; ss++) s += Kb[(size_t)ss * DIM + d];
    pp[((size_t)b * 16 + ch) * DIM + d] = s;
}

__global__ void prefix_combine(const float* __restrict__ Kmat,
                               const float* __restrict__ pp, float* __restrict__ P) {
    int b = blockIdx.x, d = threadIdx.x;
    const float* Kb = Kmat + (size_t)b * SEQ * DIM;
    float s = 0.f;
    for (int ch = 0; ch < 16; ch++) s += pp[((size_t)b * 16 + ch) * DIM + d];
    float p2047 = s;
    float p2048 = p2047 + Kb[(size_t)2047 * DIM + d];
    float p2049 = p2048 + Kb[(size_t)2048 * DIM + d];
    float p2052 = p2049 + Kb[(size_t)2049 * DIM + d]
                        + Kb[(size_t)2050 * DIM + d]
                        + Kb[(size_t)2051 * DIM + d];
    float* Pb = P + (size_t)b * 4 * DIM;
    Pb[0 * DIM + d] = p2047;
    Pb[1 * DIM + d] = p2048;
    Pb[2 * DIM + d] = p2049;
    Pb[3 * DIM + d] = p2052;
}

__global__ void sk_kernel(const float* __restrict__ Kmat, const float* __restrict__ P,
                          __nv_bfloat16* __restrict__ SK,
                          float A3, float B3, float A4, float B4, float A5, float B5) {
    int i = blockIdx.x, b = blockIdx.y, d = threadIdx.x;
    const float* Kb = Kmat + (size_t)b * SEQ * DIM;
    int lo = max(i - 2, 0), hi = min(i + 2, SEQ - 1);
    int n = hi - lo + 1;
    float band = 0.f;
    for (int j = lo; j <= hi; j++) band += Kb[(size_t)j * DIM + d];
    const float* Pb = P + (size_t)b * 4 * DIM;
    float off;
    if (i <= 2048) off = Pb[3 * DIM + d] - band;
    else           off = Pb[(5 - n) * DIM + d];
    float a, bb;
    if (n == 5)      { a = A5; bb = B5; }
    else if (n == 4) { a = A4; bb = B4; }
    else             { a = A3; bb = B3; }
    SK[((size_t)b * SEQ + i) * DIM + d] = __float2bfloat16(a * band + bb * off);
}

// ---------------- full-tensor LayerNorm ----------------
__global__ void ln_partial(const float* __restrict__ x1, const float* __restrict__ x2,
                           float* __restrict__ part) {
    int tid = threadIdx.x, bid = blockIdx.x;
    float s = 0.f, ss = 0.f;
    for (size_t i = (size_t)bid * 256 + tid; i < TXT_N; i += (size_t)2048 * 256) {
        float v = x1[i] + x2[i];
        s += v;
        ss = fmaf(v, v, ss);
    }
    __shared__ float rs[256], rss[256];
    rs[tid] = s; rss[tid] = ss;
    __syncthreads();
    for (int o = 128; o; o >>= 1) {
        if (tid < o) { rs[tid] += rs[tid + o]; rss[tid] += rss[tid + o]; }
        __syncthreads();
    }
    if (tid == 0) { part[bid] = rs[0]; part[2048 + bid] = rss[0]; }
}

__global__ void ln_combine(const float* __restrict__ part, float* __restrict__ stats) {
    __shared__ double sd[256], ssd[256];
    int tid = threadIdx.x;
    double s = 0.0, ss = 0.0;
    for (int i = tid; i < 2048; i += 256) { s += part[i]; ss += part[2048 + i]; }
    sd[tid] = s; ssd[tid] = ss;
    __syncthreads();
    for (int o = 128; o; o >>= 1) {
        if (tid < o) { sd[tid] += sd[tid + o]; ssd[tid] += ssd[tid + o]; }
        __syncthreads();
    }
    if (tid == 0) {
        double n = (double)TXT_N;
        double mu = sd[0] / n;
        double var = ssd[0] / n - mu * mu;
        stats[0] = (float)mu;
        stats[1] = (float)(1.0 / sqrt(var + 1e-6));
    }
}

__global__ void ln_apply(const float* __restrict__ x1, const float* __restrict__ x2,
                         const float* __restrict__ g, const float* __restrict__ bta,
                         const float* __restrict__ stats, float* __restrict__ out) {
    size_t i = (size_t)blockIdx.x * 256 + threadIdx.x;
    float mu = stats[0], r = stats[1];
    float v = x1[i] + x2[i];
    out[i] = (v - mu) * r * g[i] + bta[i];
}

__global__ void copy_img(const float* __restrict__ src, float* __restrict__ dst, int n) {
    int i = blockIdx.x * 256 + threadIdx.x;
    if (i < n) dst[i] = src[i];
}

// ---------------- launch ----------------
extern "C" void kernel_launch(void* const* d_in, const int* in_sizes, int n_in,
                              void* d_out, int out_size) {
    const float* text  = (const float*)d_in[0];
    const float* image = (const float*)d_in[1];
    const float* Wq = (const float*)d_in[2];
    const float* bq = (const float*)d_in[3];
    const float* Wk = (const float*)d_in[4];
    const float* bk = (const float*)d_in[5];
    const float* Wv = (const float*)d_in[6];
    const float* bv = (const float*)d_in[7];
    const float* W1 = (const float*)d_in[8];
    const float* b1 = (const float*)d_in[9];
    const float* W2 = (const float*)d_in[10];
    const float* b2 = (const float*)d_in[11];
    const float* gamma = (const float*)d_in[12];
    const float* beta  = (const float*)d_in[13];
    float* out = (float*)d_out;

    float *K, *V, *O, *H, *M2, *FF, *part, *stats, *P, *pp;
    __nv_bfloat16 *Qbf, *SKbf, *Vtbf;
    cudaGetSymbolAddress((void**)&Qbf,  g_Qbf);
    cudaGetSymbolAddress((void**)&SKbf, g_SKbf);
    cudaGetSymbolAddress((void**)&Vtbf, g_Vtbf);
    cudaGetSymbolAddress((void**)&K,  g_K);
    cudaGetSymbolAddress((void**)&V,  g_V);
    cudaGetSymbolAddress((void**)&O,  g_O);
    cudaGetSymbolAddress((void**)&H,  g_H);
    cudaGetSymbolAddress((void**)&M2, g_M2);
    cudaGetSymbolAddress((void**)&FF, g_FF);
    cudaGetSymbolAddress((void**)&part, g_part);
    cudaGetSymbolAddress((void**)&stats, g_stats);
    cudaGetSymbolAddress((void**)&P,  g_P);
    cudaGetSymbolAddress((void**)&pp, g_pp);

    static int smem_set = 0;
    if (!smem_set) {
        cudaFuncSetAttribute(tc_gemm, cudaFuncAttributeMaxDynamicSharedMemorySize, GEMM_SMEM);
        cudaFuncSetAttribute(flash_attn, cudaFuncAttributeMaxDynamicSharedMemorySize, FLASH_SMEM);
        smem_set = 1;
    }

    // sparse-softmax coefficients
    double e = exp(1.0);
    float A[6], Bc[6];
    for (int n = 3; n <= 5; n++) {
        double Z = n * e + (double)(SEQ - n);
        A[n]  = (float)(e / Z);
        Bc[n] = (float)(1.0 / Z);
    }

    // QKV projections (Q straight to bf16)
    tc_gemm<<<dim3(2, 128, 1), 256, GEMM_SMEM>>>(text, Wq, (float*)Qbf, NTOK, DIM, DIM, 0, 0, 0, 1.f, bq, 0, 1);
    tc_gemm<<<dim3(2, 128, 1), 256, GEMM_SMEM>>>(text, Wk, K, NTOK, DIM, DIM, 0, 0, 0, 1.f, bk, 0, 0);
    tc_gemm<<<dim3(2, 128, 1), 256, GEMM_SMEM>>>(text, Wv, V, NTOK, DIM, DIM, 0, 0, 0, 1.f, bv, 0, 0);

    transpose_v<<<dim3(128, 8, BATCH), dim3(32, 8)>>>(V, Vtbf);

    // analytic sparse @ K -> bf16 SK
    prefix_partial<<<dim3(16, BATCH), 256>>>(K, pp);
    prefix_combine<<<BATCH, 256>>>(K, pp, P);
    sk_kernel<<<dim3(SEQ, BATCH), 256>>>(K, P, SKbf, A[3], Bc[3], A[4], Bc[4], A[5], Bc[5]);

    // fused bf16 attention
    flash_attn<<<dim3(SEQ / FQT, BATCH), 512, FLASH_SMEM>>>(Qbf, SKbf, Vtbf, O);

    // LN1 over full tensor of (O + text) -> H
    ln_partial<<<2048, 256>>>(O, text, part);
    ln_combine<<<1, 256>>>(part, stats);
    ln_apply<<<NTOK, 256>>>(O, text, gamma, beta, stats, H);

    // MLP
    tc_gemm<<<dim3(8, 128, 1), 256, GEMM_SMEM>>>(H, W1, FF, NTOK, DFF, DIM, 0, 0, 0, 1.f, b1, 1, 0);
    tc_gemm<<<dim3(2, 128, 1), 256, GEMM_SMEM>>>(FF, W2, M2, NTOK, DIM, DFF, 0, 0, 0, 1.f, b2, 0, 0);

    // LN2 over full tensor of (M2 + text) -> out
    ln_partial<<<2048, 256>>>(M2, text, part);
    ln_combine<<<1, 256>>>(part, stats);
    ln_apply<<<NTOK, 256>>>(M2, text, gamma, beta, stats, out);

    // image passthrough
    if (out_size >= (int)TXT_N + IMG_N) {
        copy_img<<<(IMG_N + 255) / 256, 256>>>(image, out + TXT_N, IMG_N);
    }
}